// round 14
// baseline (speedup 1.0000x reference)
#include <cuda_runtime.h>
#include <cuda_fp16.h>
#include <cstdint>

static constexpr int NCAND = 7;

// =====================================================================
// Device scratch (allocation-free: __device__ globals)
// =====================================================================
__device__ int      g_flag;            // chosen metadata layout, NCAND = none
__device__ int      g_ok;              // sparse result verified?
__device__ __half   g_actc[16777216];  // 32768 x 512 compressed 2:4 fp16
__device__ uint32_t g_meta[1048576];   // PRECOMPOSED meta: [mb][kw][16]
__device__ uint32_t g_can[1048576];    // canonical meta words [row][kw]
__device__ __half   g_actd[33554432];  // dense fp16 (built only on fallback)
__device__ __half   g_wt[1048576];     // 1024 x 1024 fp16 weight

// =====================================================================
// Helpers (base ISA only)
// =====================================================================
__device__ __forceinline__ void cp16(void* s, const void* g) {
    uint32_t sa = (uint32_t)__cvta_generic_to_shared(s);
    asm volatile("cp.async.cg.shared.global [%0], [%1], 16;"
                 :: "r"(sa), "l"(g) : "memory");
}
__device__ __forceinline__ void cp_commit() {
    asm volatile("cp.async.commit_group;" ::: "memory");
}
template <int N>
__device__ __forceinline__ void cp_wait() {
    asm volatile("cp.async.wait_group %0;" :: "n"(N) : "memory");
}
__device__ __forceinline__ void ldsm_x4(uint32_t* r, uint32_t addr) {
    asm volatile("ldmatrix.sync.aligned.m8n8.x4.shared.b16 {%0,%1,%2,%3}, [%4];"
                 : "=r"(r[0]), "=r"(r[1]), "=r"(r[2]), "=r"(r[3]) : "r"(addr));
}
__device__ __forceinline__ uint32_t lds32(uint32_t addr) {
    uint32_t v;
    asm volatile("ld.shared.u32 %0, [%1];" : "=r"(v) : "r"(addr));
    return v;
}
__device__ __forceinline__ void mma_f16(float* d, const uint32_t* a,
                                        const uint32_t* b) {
    asm volatile(
        "mma.sync.aligned.m16n8k16.row.col.f32.f16.f16.f32 "
        "{%0,%1,%2,%3}, {%4,%5,%6,%7}, {%8,%9}, {%0,%1,%2,%3};"
        : "+f"(d[0]), "+f"(d[1]), "+f"(d[2]), "+f"(d[3])
        : "r"(a[0]), "r"(a[1]), "r"(a[2]), "r"(a[3]), "r"(b[0]), "r"(b[1]));
}
__device__ __forceinline__ void mma_spo(float* d, const uint32_t* a,
                                        const uint32_t* b, uint32_t e) {
    asm volatile(
        "mma.sp::ordered_metadata.sync.aligned.m16n8k32.row.col.f32.f16.f16.f32 "
        "{%0,%1,%2,%3}, {%4,%5,%6,%7}, {%8,%9,%10,%11}, {%0,%1,%2,%3}, %12, 0x0;"
        : "+f"(d[0]), "+f"(d[1]), "+f"(d[2]), "+f"(d[3])
        : "r"(a[0]), "r"(a[1]), "r"(a[2]), "r"(a[3]),
          "r"(b[0]), "r"(b[1]), "r"(b[2]), "r"(b[3]), "r"(e));
}
__device__ __forceinline__ void mma_spp(float* d, const uint32_t* a,
                                        const uint32_t* b, uint32_t e) {
    asm volatile(
        "mma.sp.sync.aligned.m16n8k32.row.col.f32.f16.f16.f32 "
        "{%0,%1,%2,%3}, {%4,%5,%6,%7}, {%8,%9,%10,%11}, {%0,%1,%2,%3}, %12, 0x0;"
        : "+f"(d[0]), "+f"(d[1]), "+f"(d[2]), "+f"(d[3])
        : "r"(a[0]), "r"(a[1]), "r"(a[2]), "r"(a[3]),
          "r"(b[0]), "r"(b[1]), "r"(b[2]), "r"(b[3]), "r"(e));
}

__device__ __forceinline__ uint32_t nibble_ilv(uint32_t x, uint32_t y) {
    return (x & 0xFu) | ((y & 0xFu) << 4) | ((x & 0xF0u) << 4) | ((y & 0xF0u) << 8)
         | ((x & 0xF00u) << 8) | ((y & 0xF00u) << 12)
         | ((x & 0xF000u) << 12) | ((y & 0xF000u) << 16);
}
__device__ __forceinline__ uint32_t compose_meta(int fl, uint32_t wg,
                                                 uint32_t wg8, int jpar) {
    uint32_t x = (wg  >> (16 * jpar)) & 0xFFFFu;
    uint32_t y = (wg8 >> (16 * jpar)) & 0xFFFFu;
    switch (fl) {
        case 0: return x | (y << 16);        // ordered, half-split
        case 1: return nibble_ilv(x, y);     // ordered, nibble-interleave
        case 2: return jpar ? wg8 : wg;      // ordered, P0
        case 3: return jpar ? wg : wg8;      // ordered, P0 swapped
        case 4: return y | (x << 16);        // ordered, half-split swapped
        case 5: return jpar ? wg8 : wg;      // plain mma.sp, P0
        case 6: return x | (y << 16);        // plain mma.sp, half-split
    }
    return 0;
}

// =====================================================================
// Probe: ISA-level metadata layout discovery (register-fed metadata).
// =====================================================================
__global__ void probe_kernel() {
    __shared__ char     AsmB[16 * 80];
    __shared__ char     BsmB[8 * 144];
    __shared__ uint32_t can[16];
    __shared__ float    Alog[16 * 32];
    __shared__ float    Wlog[8 * 32];

    const int lane = threadIdx.x & 31;

    for (int i = lane; i < 16 * 80 / 4; i += 32) ((uint32_t*)AsmB)[i] = 0;
    for (int i = lane; i < 16 * 32; i += 32) Alog[i] = 0.f;
    __syncwarp();

    if (lane < 16) {
        const int r = lane;
        const int pe0[6] = {0, 0, 0, 1, 1, 2};
        const int pe1[6] = {1, 2, 3, 2, 3, 3};
        uint32_t word = 0;
        for (int gg = 0; gg < 8; gg++) {
            int p  = (r * 8 + gg) % 6;
            int e0 = pe0[p], e1 = pe1[p];
            word |= (uint32_t)(e0 | (e1 << 2)) << (4 * gg);
            int k0 = 4 * gg + e0, k1 = 4 * gg + e1;
            float v0 = ((float)((r * 32 + k0) % 19) - 9.f) * 0.125f;
            float v1 = ((float)((r * 32 + k1) % 19) - 9.f) * 0.125f;
            Alog[r * 32 + k0] = v0;
            Alog[r * 32 + k1] = v1;
            *(__half*)(AsmB + r * 80 + (2 * gg + 0) * 2) = __float2half(v0);
            *(__half*)(AsmB + r * 80 + (2 * gg + 1) * 2) = __float2half(v1);
        }
        can[r] = word;
    }
    if (lane < 8) {
        const int n = lane;
        for (int k = 0; k < 32; k++) {
            float wv = ((float)((k * 8 + n) % 23) - 11.f) * 0.0625f;
            Wlog[n * 32 + k] = wv;
            *(__half*)(BsmB + n * 144 + k * 2) = __float2half(wv);
        }
    }
    __syncwarp();

    const int j8 = lane >> 3, r8 = lane & 7;
    uint32_t abase = (uint32_t)__cvta_generic_to_shared(AsmB)
                   + (uint32_t)(((j8 & 1) * 8 + r8) * 80 + (j8 >> 1) * 16);
    uint32_t bbase = (uint32_t)__cvta_generic_to_shared(BsmB)
                   + (uint32_t)(r8 * 144 + j8 * 16);
    uint32_t a[4], b[4];
    ldsm_x4(a, abase);
    ldsm_x4(b, bbase);

    const int g = lane >> 2, q = lane & 3;
    float e[4];
    #pragma unroll
    for (int h = 0; h < 4; h++) {
        int r = g + (h >> 1) * 8;
        int n = 2 * q + (h & 1);
        float sum = 0.f;
        for (int k = 0; k < 32; k++) sum += Alog[r * 32 + k] * Wlog[n * 32 + k];
        e[h] = sum;
    }

    const int jpar = lane & 1;
    uint32_t wg = can[g], wg8 = can[g + 8];

    int chosen = NCAND;
    for (int c = 0; c < NCAND; c++) {
        uint32_t E = compose_meta(c, wg, wg8, jpar);
        float d[4] = {0.f, 0.f, 0.f, 0.f};
        if (c >= 5) mma_spp(d, a, b, E);
        else        mma_spo(d, a, b, E);
        bool ok = true;
        #pragma unroll
        for (int h = 0; h < 4; h++) ok &= fabsf(d[h] - e[h]) < 0.01f;
        if (__all_sync(0xFFFFFFFFu, ok) && chosen == NCAND) chosen = c;
    }
    if (lane == 0) { g_flag = chosen; g_ok = 1; }
}

// =====================================================================
// Kernel 1: prune + rescale + canonical meta + meta PRECOMPOSE.
// Blocks 0..2047: 16 rows each. Blocks 2048..2175: weight fp32->fp16.
// =====================================================================
__global__ void __launch_bounds__(512) prep_kernel(const float* __restrict__ x,
                                                   const float* __restrict__ wsrc) {
    const int tid  = threadIdx.x;

    if (blockIdx.x >= 2048) {              // fused weight conversion
        int base = (blockIdx.x - 2048) * 512 + tid;   // 65536 threads
        #pragma unroll
        for (int j = 0; j < 4; j++) {
            int i = base * 4 + j;          // float4 index, 262144 total
            float4 v = reinterpret_cast<const float4*>(wsrc)[i];
            __half2 h0 = __floats2half2_rn(v.x, v.y);
            __half2 h1 = __floats2half2_rn(v.z, v.w);
            uint2 u;
            u.x = *reinterpret_cast<uint32_t*>(&h0);
            u.y = *reinterpret_cast<uint32_t*>(&h1);
            reinterpret_cast<uint2*>(g_wt)[i] = u;
        }
        return;
    }

    __shared__ uint32_t canw[16 * 32];     // canonical words [row_in_block][kw]
    const int wid  = tid >> 5;
    const int lane = tid & 31;
    const int row  = blockIdx.x * 16 + wid;
    const float4* src = reinterpret_cast<const float4*>(x + (size_t)row * 1024);

    float k0v[8], k1v[8];
    int   nib[8];
    float s = 0.f, ss = 0.f, ps = 0.f, pss = 0.f;
    #pragma unroll
    for (int jj = 0; jj < 8; jj++) {
        const float4 g4 = src[lane + 32 * jj];
        float v0 = g4.x, v1 = g4.y, v2 = g4.z, v3 = g4.w;
        float a0 = fabsf(v0), a1 = fabsf(v1), a2 = fabsf(v2), a3 = fabsf(v3);
        int r0 = (a1 >  a0) + (a2 >  a0) + (a3 >  a0);
        int r1 = (a0 >= a1) + (a2 >  a1) + (a3 >  a1);
        int r2 = (a0 >= a2) + (a1 >= a2) + (a3 >  a2);
        int r3 = (a0 >= a3) + (a1 >= a3) + (a2 >= a3);
        bool q0 = r0 < 2, q1 = r1 < 2, q2 = r2 < 2, q3 = r3 < 2;
        int e0 = q0 ? 0 : (q1 ? 1 : 2);
        int e1 = q3 ? 3 : (q2 ? 2 : 1);
        float kv0 = q0 ? v0 : (q1 ? v1 : v2);
        float kv1 = q3 ? v3 : (q2 ? v2 : v1);
        k0v[jj] = kv0; k1v[jj] = kv1;
        nib[jj] = e0 | (e1 << 2);
        s   += v0 + v1 + v2 + v3;
        ss  += v0*v0 + v1*v1 + v2*v2 + v3*v3;
        ps  += kv0 + kv1;
        pss += kv0*kv0 + kv1*kv1;
    }
    #pragma unroll
    for (int off = 16; off; off >>= 1) {
        s   += __shfl_xor_sync(0xFFFFFFFFu, s,   off);
        ss  += __shfl_xor_sync(0xFFFFFFFFu, ss,  off);
        ps  += __shfl_xor_sync(0xFFFFFFFFu, ps,  off);
        pss += __shfl_xor_sync(0xFFFFFFFFu, pss, off);
    }
    float varx = (ss  - s  * s  * (1.f / 1024.f)) * (1.f / 1023.f);
    float varp = (pss - ps * ps * (1.f / 1024.f)) * (1.f / 1023.f);
    varp = fmaxf(varp, 1e-9f);
    const float sc = sqrtf(varx / varp);

    uint32_t* dc = reinterpret_cast<uint32_t*>(g_actc + (size_t)row * 512);
    #pragma unroll
    for (int jj = 0; jj < 8; jj++) {
        __half2 hc = __floats2half2_rn(sc * k0v[jj], sc * k1v[jj]);
        dc[lane + 32 * jj] = *reinterpret_cast<uint32_t*>(&hc);

        uint32_t m = (uint32_t)nib[jj] << (4 * (lane & 7));
        m |= __shfl_xor_sync(0xFFFFFFFFu, m, 1);
        m |= __shfl_xor_sync(0xFFFFFFFFu, m, 2);
        m |= __shfl_xor_sync(0xFFFFFFFFu, m, 4);
        if ((lane & 7) == 0)
            canw[wid * 32 + 4 * jj + (lane >> 3)] = m;
    }
    __syncthreads();

    // canonical words to global (for verify/densify):
    g_can[(size_t)blockIdx.x * 512 + tid] = canw[tid];

    // Compose: each thread emits one final per-thread metadata word.
    // Output layout: g_meta[(mb*32 + kw)*16 + (g*2 + jpar)]
    const int fl   = g_flag;
    const int kw   = tid >> 4;
    const int idx  = tid & 15;
    const int g    = idx >> 1;
    const int jpar = idx & 1;
    uint32_t wg  = canw[g * 32 + kw];
    uint32_t wg8 = canw[(g + 8) * 32 + kw];
    g_meta[((size_t)blockIdx.x * 32 + kw) * 16 + idx] =
        compose_meta(fl, wg, wg8, jpar);
}

// =====================================================================
// Kernel 3a: SPARSE GEMM. CTA 128x128, warp 64x32, 3 stages, 2 CTAs/SM.
// E loads hoisted per-tile; A fragments for kk=1 prefetched during kk=0;
// B fragments double-buffered per nt.
// =====================================================================
static constexpr int SA_ROWB = 80;
static constexpr int SB_ROWB = 144;
static constexpr int SA_BYTES = 128 * SA_ROWB;   // 10240
static constexpr int SB_BYTES = 128 * SB_ROWB;   // 18432
static constexpr int SOFF_B = SA_BYTES;
static constexpr int SOFF_M = SA_BYTES + SB_BYTES;
static constexpr int SSTAGE = SOFF_M + 1024;     // 29696
static constexpr unsigned SSMEM = 3 * SSTAGE;    // 89088

__global__ void __launch_bounds__(256, 2) gemm_sparse(float* __restrict__ C) {
    const int fl = g_flag;
    if (fl >= NCAND) return;

    extern __shared__ char smem[];
    const int tid  = threadIdx.x;
    const int lane = tid & 31;
    const int w    = tid >> 5;
    const int wm   = w & 1;
    const int wn   = w >> 1;
    const int g    = lane >> 2;
    const int t    = lane & 3;
    const int jpar = lane & 1;

    const int m0 = blockIdx.y * 128;
    const int n0 = blockIdx.x * 128;

    float acc[4][4][4];
    #pragma unroll
    for (int i = 0; i < 4; i++)
        #pragma unroll
        for (int jj = 0; jj < 4; jj++)
            #pragma unroll
            for (int q = 0; q < 4; q++) acc[i][jj][q] = 0.f;

    const __half*   Agb = g_actc + (size_t)m0 * 512;
    const __half*   Bgb = g_wt   + (size_t)n0 * 1024;
    const uint32_t* Mgb = g_meta + (size_t)(m0 >> 4) * 512;

    const uint32_t smem_base = (uint32_t)__cvta_generic_to_shared(smem);
    const int j8 = lane >> 3, r8 = lane & 7;
    const uint32_t a_lane_off =
        (uint32_t)((wm * 64 + (j8 & 1) * 8 + r8) * SA_ROWB + (j8 >> 1) * 16);
    const uint32_t b_lane_off = (uint32_t)(SOFF_B + r8 * SB_ROWB + j8 * 16);
    const uint32_t m_lane_off = (uint32_t)(SOFF_M + (g * 2 + jpar) * 4);

    auto load_stage = [&](int kt, int st_i) {
        char* st = smem + st_i * SSTAGE;
        const __half* Ag = Agb + kt * 32;
        const __half* Bg = Bgb + kt * 64;
        #pragma unroll
        for (int i = 0; i < 2; i++) {
            int ch = tid + i * 256;
            int r = ch >> 2, c = ch & 3;
            cp16(st + r * SA_ROWB + c * 16, Ag + (size_t)r * 512 + c * 8);
        }
        #pragma unroll
        for (int i = 0; i < 4; i++) {
            int ch = tid + i * 256;
            int r = ch >> 3, c = ch & 7;
            cp16(st + SOFF_B + r * SB_ROWB + c * 16, Bg + (size_t)r * 1024 + c * 8);
        }
        if (tid < 64) {
            int mb = tid >> 3, c = tid & 7;
            cp16(st + SOFF_M + mb * 128 + c * 16,
                 Mgb + ((size_t)mb * 32 + kt * 2) * 16 + c * 4);
        }
        cp_commit();
    };

    load_stage(0, 0);
    load_stage(1, 1);

    for (int kt = 0; kt < 16; kt++) {
        cp_wait<1>();
        __syncthreads();

        if (kt + 2 < 16) load_stage(kt + 2, (kt + 2) % 3);

        const uint32_t st = smem_base + (uint32_t)((kt % 3) * SSTAGE);

        // ---- hoisted E loads (both kk), overlap with A ldsm batch ----
        uint32_t E0[4], E1[4];
        {
            const uint32_t me = st + m_lane_off + (uint32_t)(wm * 4 * 128);
            #pragma unroll
            for (int mt = 0; mt < 4; mt++) {
                E0[mt] = lds32(me + (uint32_t)(mt * 128));
                E1[mt] = lds32(me + (uint32_t)(mt * 128 + 64));
            }
        }
        // ---- kk=0 A fragments ----
        uint32_t a0[4][4], a1[4][4];
        #pragma unroll
        for (int mt = 0; mt < 4; mt++)
            ldsm_x4(a0[mt], st + a_lane_off + mt * (16 * SA_ROWB));

        const uint32_t bb0 = st + b_lane_off + (uint32_t)(wn * 32 * SB_ROWB);
        uint32_t b2[2][4];
        ldsm_x4(b2[0], bb0);

        if (fl >= 5) {
            // ---- kk=0 (prefetch a1 after first mma group) ----
            #pragma unroll
            for (int nt = 0; nt < 4; nt++) {
                if (nt < 3) ldsm_x4(b2[(nt + 1) & 1], bb0 + (nt + 1) * 8 * SB_ROWB);
                #pragma unroll
                for (int mt = 0; mt < 4; mt++)
                    mma_spp(acc[mt][nt], a0[mt], b2[nt & 1], E0[mt]);
                if (nt == 0) {
                    #pragma unroll
                    for (int mt = 0; mt < 4; mt++)
                        ldsm_x4(a1[mt], st + a_lane_off + mt * (16 * SA_ROWB) + 32);
                }
            }
            // ---- kk=1 ----
            ldsm_x4(b2[0], bb0 + 64);
            #pragma unroll
            for (int nt = 0; nt < 4; nt++) {
                if (nt < 3)
                    ldsm_x4(b2[(nt + 1) & 1], bb0 + 64 + (nt + 1) * 8 * SB_ROWB);
                #pragma unroll
                for (int mt = 0; mt < 4; mt++)
                    mma_spp(acc[mt][nt], a1[mt], b2[nt & 1], E1[mt]);
            }
        } else {
            #pragma unroll
            for (int nt = 0; nt < 4; nt++) {
                if (nt < 3) ldsm_x4(b2[(nt + 1) & 1], bb0 + (nt + 1) * 8 * SB_ROWB);
                #pragma unroll
                for (int mt = 0; mt < 4; mt++)
                    mma_spo(acc[mt][nt], a0[mt], b2[nt & 1], E0[mt]);
                if (nt == 0) {
                    #pragma unroll
                    for (int mt = 0; mt < 4; mt++)
                        ldsm_x4(a1[mt], st + a_lane_off + mt * (16 * SA_ROWB) + 32);
                }
            }
            ldsm_x4(b2[0], bb0 + 64);
            #pragma unroll
            for (int nt = 0; nt < 4; nt++) {
                if (nt < 3)
                    ldsm_x4(b2[(nt + 1) & 1], bb0 + 64 + (nt + 1) * 8 * SB_ROWB);
                #pragma unroll
                for (int mt = 0; mt < 4; mt++)
                    mma_spo(acc[mt][nt], a1[mt], b2[nt & 1], E1[mt]);
            }
        }
    }

    #pragma unroll
    for (int mt = 0; mt < 4; mt++) {
        const int row = m0 + wm * 64 + mt * 16 + g;
        #pragma unroll
        for (int nt = 0; nt < 4; nt++) {
            const int col = n0 + wn * 32 + nt * 8 + 2 * t;
            float2 v0 = make_float2(acc[mt][nt][0], acc[mt][nt][1]);
            float2 v1 = make_float2(acc[mt][nt][2], acc[mt][nt][3]);
            *reinterpret_cast<float2*>(&C[(size_t)row * 1024 + col])       = v0;
            *reinterpret_cast<float2*>(&C[(size_t)(row + 8) * 1024 + col]) = v1;
        }
    }
}

// =====================================================================
// Kernel 4: verify (slim). 128 blocks = 16 rows x 8 n-chunks; 16 cols
// per block, offsets vary per row -> all positions mod 16 covered.
// =====================================================================
__global__ void __launch_bounds__(256) verify_kernel(const float* __restrict__ C) {
    if (g_flag >= NCAND) {
        if (blockIdx.x == 0 && threadIdx.x == 0) g_ok = 0;
        return;
    }
    __shared__ __half arow[1024];
    const int tid  = threadIdx.x;
    const int wid  = tid >> 5;
    const int lane = tid & 31;
    const int rsel = blockIdx.x >> 3;
    const int row  = rsel * 2048 + ((rsel * 1337) & 2047);
    const int colbase = (blockIdx.x & 7) * 128;

    {
        uint32_t pair = reinterpret_cast<const uint32_t*>(
                            g_actc + (size_t)row * 512)[tid];
        uint32_t word = g_can[(size_t)row * 32 + (tid >> 3)];
        uint32_t nb = (word >> (4 * (tid & 7))) & 0xFu;
        int e0 = nb & 3, e1 = (nb >> 2) & 3;
        __half2 hv = *reinterpret_cast<__half2*>(&pair);
        __half z = __float2half(0.f);
        __half v[4] = { z, z, z, z };
        v[e0] = __low2half(hv);
        v[e1] = __high2half(hv);
        arow[4 * tid + 0] = v[0];
        arow[4 * tid + 1] = v[1];
        arow[4 * tid + 2] = v[2];
        arow[4 * tid + 3] = v[3];
    }
    __syncthreads();

    const __half2* a2 = reinterpret_cast<const __half2*>(arow);
    #pragma unroll
    for (int c0 = 0; c0 < 2; c0++) {
        const int col = colbase + wid * 16 + c0 * 8 + (rsel & 7);
        const __half2* w2 =
            reinterpret_cast<const __half2*>(g_wt + (size_t)col * 1024);
        float sum = 0.f;
        for (int k = lane; k < 512; k += 32) {
            float2 af = __half22float2(a2[k]);
            float2 wf = __half22float2(w2[k]);
            sum = fmaf(af.x, wf.x, fmaf(af.y, wf.y, sum));
        }
        #pragma unroll
        for (int off = 16; off; off >>= 1)
            sum += __shfl_xor_sync(0xFFFFFFFFu, sum, off);
        if (lane == 0) {
            float got = C[(size_t)row * 1024 + col];
            if (fabsf(got - sum) > 0.02f * (fabsf(sum) + 0.25f)) g_ok = 0;
        }
    }
}

// =====================================================================
// Kernel 5: densify (iff !g_ok). Grid 2048 (noop cost 1/4 of before).
// =====================================================================
__global__ void __launch_bounds__(256) densify_kernel() {
    if (g_ok) return;
    #pragma unroll
    for (int i = 0; i < 16; i++) {
        int gi = (blockIdx.x * 16 + i) * 256 + threadIdx.x;
        int row = gi >> 8, gg = gi & 255;
        uint32_t pair = reinterpret_cast<const uint32_t*>(
                            g_actc + (size_t)row * 512)[gg];
        uint32_t word = g_can[(size_t)row * 32 + (gg >> 3)];
        uint32_t nb = (word >> (4 * (gg & 7))) & 0xFu;
        int e0 = nb & 3, e1 = (nb >> 2) & 3;
        __half2 hv = *reinterpret_cast<__half2*>(&pair);
        __half z = __float2half(0.f);
        __half v[4] = { z, z, z, z };
        v[e0] = __low2half(hv);
        v[e1] = __high2half(hv);
        __half2 lo = __halves2half2(v[0], v[1]);
        __half2 hi = __halves2half2(v[2], v[3]);
        uint2 o;
        o.x = *reinterpret_cast<uint32_t*>(&lo);
        o.y = *reinterpret_cast<uint32_t*>(&hi);
        reinterpret_cast<uint2*>(g_actd)[gi] = o;
    }
}

// =====================================================================
// Kernel 3b: DENSE GEMM fallback (iff !g_ok). Proven R5 kernel.
// =====================================================================
static constexpr int DLDH = 40;
static constexpr int DA_ELTS = 128 * DLDH;
static constexpr int DSTAGE_ELTS = 2 * DA_ELTS;
static constexpr unsigned DSMEM = 4 * DSTAGE_ELTS * 2;           // 81920

__global__ void __launch_bounds__(256, 2) gemm_dense(float* __restrict__ C) {
    if (g_ok) return;

    extern __shared__ __half dsm[];
    const int tid  = threadIdx.x;
    const int lane = tid & 31;
    const int w    = tid >> 5;
    const int wm   = w & 1;
    const int wn   = w >> 1;
    const int g    = lane >> 2;
    const int t    = lane & 3;

    const int m0 = blockIdx.y * 128;
    const int n0 = blockIdx.x * 128;

    float acc[4][4][4];
    #pragma unroll
    for (int i = 0; i < 4; i++)
        #pragma unroll
        for (int jj = 0; jj < 4; jj++)
            #pragma unroll
            for (int q = 0; q < 4; q++) acc[i][jj][q] = 0.f;

    const __half* Agb = g_actd + (size_t)m0 * 1024;
    const __half* Bgb = g_wt   + (size_t)n0 * 1024;
    const uint32_t smem_base = (uint32_t)__cvta_generic_to_shared(dsm);

    const int j8 = lane >> 3, r8 = lane & 7;
    const uint32_t a_lane_off =
        (uint32_t)((wm * 64 + (j8 & 1) * 8 + r8) * 80 + (j8 >> 1) * 16);
    const uint32_t b_lane_off =
        (uint32_t)(DA_ELTS * 2 + (wn * 32 + (j8 >> 1) * 8 + r8) * 80 + (j8 & 1) * 16);

    auto load_stage = [&](int kt, int st_i) {
        __half* As = dsm + st_i * DSTAGE_ELTS;
        __half* Bs = As + DA_ELTS;
        const __half* Ag = Agb + kt * 32;
        const __half* Bg = Bgb + kt * 32;
        #pragma unroll
        for (int i = 0; i < 2; i++) {
            int ch = tid + i * 256;
            int r = ch >> 2, c = ch & 3;
            cp16(As + r * DLDH + c * 8, Ag + (size_t)r * 1024 + c * 8);
        }
        #pragma unroll
        for (int i = 0; i < 2; i++) {
            int ch = tid + i * 256;
            int r = ch >> 2, c = ch & 3;
            cp16(Bs + r * DLDH + c * 8, Bg + (size_t)r * 1024 + c * 8);
        }
        cp_commit();
    };

    load_stage(0, 0);
    load_stage(1, 1);
    load_stage(2, 2);

    for (int kt = 0; kt < 32; kt++) {
        cp_wait<2>();
        __syncthreads();

        if (kt + 3 < 32) load_stage(kt + 3, (kt + 3) & 3);

        const uint32_t st = smem_base + (uint32_t)((kt & 3) * DSTAGE_ELTS * 2);
        const uint32_t abase = st + a_lane_off;
        const uint32_t bbase = st + b_lane_off;

        #pragma unroll
        for (int kk = 0; kk < 2; kk++) {
            uint32_t a[4][4];
            #pragma unroll
            for (int mt = 0; mt < 4; mt++)
                ldsm_x4(a[mt], abase + mt * (16 * 80) + kk * 32);
            uint32_t b[2][4];
            #pragma unroll
            for (int np = 0; np < 2; np++)
                ldsm_x4(b[np], bbase + np * (16 * 80) + kk * 32);
            #pragma unroll
            for (int mt = 0; mt < 4; mt++)
                #pragma unroll
                for (int nt = 0; nt < 4; nt++)
                    mma_f16(acc[mt][nt], a[mt], &b[nt >> 1][(nt & 1) * 2]);
        }
    }

    #pragma unroll
    for (int mt = 0; mt < 4; mt++) {
        const int row = m0 + wm * 64 + mt * 16 + g;
        #pragma unroll
        for (int nt = 0; nt < 4; nt++) {
            const int col = n0 + wn * 32 + nt * 8 + 2 * t;
            float2 v0 = make_float2(acc[mt][nt][0], acc[mt][nt][1]);
            float2 v1 = make_float2(acc[mt][nt][2], acc[mt][nt][3]);
            *reinterpret_cast<float2*>(&C[(size_t)row * 1024 + col])       = v0;
            *reinterpret_cast<float2*>(&C[(size_t)(row + 8) * 1024 + col]) = v1;
        }
    }
}

// =====================================================================
// Host launcher
// =====================================================================
extern "C" void kernel_launch(void* const* d_in, const int* in_sizes, int n_in,
                              void* d_out, int out_size) {
    const float* x = (const float*)d_in[0];
    const float* w = (const float*)d_in[1];
    if (n_in >= 2 && in_sizes[0] == 1048576 && in_sizes[1] != 1048576) {
        const float* tswap = x; x = w; w = tswap;
    }
    float* out = (float*)d_out;

    probe_kernel<<<1, 32>>>();
    prep_kernel<<<2176, 512>>>(x, w);     // 2048 act blocks + 128 weight blocks

    cudaFuncSetAttribute(gemm_sparse,
                         cudaFuncAttributeMaxDynamicSharedMemorySize, SSMEM);
    cudaFuncSetAttribute(gemm_dense,
                         cudaFuncAttributeMaxDynamicSharedMemorySize, DSMEM);

    gemm_sparse<<<dim3(8, 256), 256, SSMEM>>>(out);
    verify_kernel<<<128, 256>>>(out);
    densify_kernel<<<2048, 256>>>();
    gemm_dense<<<dim3(8, 256), 256, DSMEM>>>(out);
}

// round 15
// speedup vs baseline: 1.0711x; 1.0711x over previous
#include <cuda_runtime.h>
#include <cuda_fp16.h>
#include <cstdint>

static constexpr int NCAND = 7;

// =====================================================================
// Device scratch (allocation-free: __device__ globals)
// =====================================================================
__device__ int      g_flag;            // chosen metadata layout, NCAND = none
__device__ int      g_ok;              // sparse result verified?
__device__ __half   g_actc[16777216];  // 32768 x 512 compressed 2:4 fp16
__device__ uint32_t g_meta[1048576];   // PRECOMPOSED meta: [mb][kw][16]
__device__ uint32_t g_can[1048576];    // canonical meta words [row][kw]
__device__ __half   g_actd[33554432];  // dense fp16 (built only on fallback)
__device__ __half   g_wt[1048576];     // 1024 x 1024 fp16 weight

// =====================================================================
// Helpers (base ISA only)
// =====================================================================
__device__ __forceinline__ void cp16(void* s, const void* g) {
    uint32_t sa = (uint32_t)__cvta_generic_to_shared(s);
    asm volatile("cp.async.cg.shared.global [%0], [%1], 16;"
                 :: "r"(sa), "l"(g) : "memory");
}
__device__ __forceinline__ void cp_commit() {
    asm volatile("cp.async.commit_group;" ::: "memory");
}
template <int N>
__device__ __forceinline__ void cp_wait() {
    asm volatile("cp.async.wait_group %0;" :: "n"(N) : "memory");
}
__device__ __forceinline__ void ldsm_x4(uint32_t* r, uint32_t addr) {
    asm volatile("ldmatrix.sync.aligned.m8n8.x4.shared.b16 {%0,%1,%2,%3}, [%4];"
                 : "=r"(r[0]), "=r"(r[1]), "=r"(r[2]), "=r"(r[3]) : "r"(addr));
}
__device__ __forceinline__ uint32_t lds32(uint32_t addr) {
    uint32_t v;
    asm volatile("ld.shared.u32 %0, [%1];" : "=r"(v) : "r"(addr));
    return v;
}
__device__ __forceinline__ void mma_f16(float* d, const uint32_t* a,
                                        const uint32_t* b) {
    asm volatile(
        "mma.sync.aligned.m16n8k16.row.col.f32.f16.f16.f32 "
        "{%0,%1,%2,%3}, {%4,%5,%6,%7}, {%8,%9}, {%0,%1,%2,%3};"
        : "+f"(d[0]), "+f"(d[1]), "+f"(d[2]), "+f"(d[3])
        : "r"(a[0]), "r"(a[1]), "r"(a[2]), "r"(a[3]), "r"(b[0]), "r"(b[1]));
}
__device__ __forceinline__ void mma_spo(float* d, const uint32_t* a,
                                        const uint32_t* b, uint32_t e) {
    asm volatile(
        "mma.sp::ordered_metadata.sync.aligned.m16n8k32.row.col.f32.f16.f16.f32 "
        "{%0,%1,%2,%3}, {%4,%5,%6,%7}, {%8,%9,%10,%11}, {%0,%1,%2,%3}, %12, 0x0;"
        : "+f"(d[0]), "+f"(d[1]), "+f"(d[2]), "+f"(d[3])
        : "r"(a[0]), "r"(a[1]), "r"(a[2]), "r"(a[3]),
          "r"(b[0]), "r"(b[1]), "r"(b[2]), "r"(b[3]), "r"(e));
}
__device__ __forceinline__ void mma_spp(float* d, const uint32_t* a,
                                        const uint32_t* b, uint32_t e) {
    asm volatile(
        "mma.sp.sync.aligned.m16n8k32.row.col.f32.f16.f16.f32 "
        "{%0,%1,%2,%3}, {%4,%5,%6,%7}, {%8,%9,%10,%11}, {%0,%1,%2,%3}, %12, 0x0;"
        : "+f"(d[0]), "+f"(d[1]), "+f"(d[2]), "+f"(d[3])
        : "r"(a[0]), "r"(a[1]), "r"(a[2]), "r"(a[3]),
          "r"(b[0]), "r"(b[1]), "r"(b[2]), "r"(b[3]), "r"(e));
}

__device__ __forceinline__ uint32_t nibble_ilv(uint32_t x, uint32_t y) {
    return (x & 0xFu) | ((y & 0xFu) << 4) | ((x & 0xF0u) << 4) | ((y & 0xF0u) << 8)
         | ((x & 0xF00u) << 8) | ((y & 0xF00u) << 12)
         | ((x & 0xF000u) << 12) | ((y & 0xF000u) << 16);
}
__device__ __forceinline__ uint32_t compose_meta(int fl, uint32_t wg,
                                                 uint32_t wg8, int jpar) {
    uint32_t x = (wg  >> (16 * jpar)) & 0xFFFFu;
    uint32_t y = (wg8 >> (16 * jpar)) & 0xFFFFu;
    switch (fl) {
        case 0: return x | (y << 16);        // ordered, half-split
        case 1: return nibble_ilv(x, y);     // ordered, nibble-interleave
        case 2: return jpar ? wg8 : wg;      // ordered, P0
        case 3: return jpar ? wg : wg8;      // ordered, P0 swapped
        case 4: return y | (x << 16);        // ordered, half-split swapped
        case 5: return jpar ? wg8 : wg;      // plain mma.sp, P0
        case 6: return x | (y << 16);        // plain mma.sp, half-split
    }
    return 0;
}

// =====================================================================
// Probe: ISA-level metadata layout discovery (register-fed metadata).
// =====================================================================
__global__ void probe_kernel() {
    __shared__ char     AsmB[16 * 80];
    __shared__ char     BsmB[8 * 144];
    __shared__ uint32_t can[16];
    __shared__ float    Alog[16 * 32];
    __shared__ float    Wlog[8 * 32];

    const int lane = threadIdx.x & 31;

    for (int i = lane; i < 16 * 80 / 4; i += 32) ((uint32_t*)AsmB)[i] = 0;
    for (int i = lane; i < 16 * 32; i += 32) Alog[i] = 0.f;
    __syncwarp();

    if (lane < 16) {
        const int r = lane;
        const int pe0[6] = {0, 0, 0, 1, 1, 2};
        const int pe1[6] = {1, 2, 3, 2, 3, 3};
        uint32_t word = 0;
        for (int gg = 0; gg < 8; gg++) {
            int p  = (r * 8 + gg) % 6;
            int e0 = pe0[p], e1 = pe1[p];
            word |= (uint32_t)(e0 | (e1 << 2)) << (4 * gg);
            int k0 = 4 * gg + e0, k1 = 4 * gg + e1;
            float v0 = ((float)((r * 32 + k0) % 19) - 9.f) * 0.125f;
            float v1 = ((float)((r * 32 + k1) % 19) - 9.f) * 0.125f;
            Alog[r * 32 + k0] = v0;
            Alog[r * 32 + k1] = v1;
            *(__half*)(AsmB + r * 80 + (2 * gg + 0) * 2) = __float2half(v0);
            *(__half*)(AsmB + r * 80 + (2 * gg + 1) * 2) = __float2half(v1);
        }
        can[r] = word;
    }
    if (lane < 8) {
        const int n = lane;
        for (int k = 0; k < 32; k++) {
            float wv = ((float)((k * 8 + n) % 23) - 11.f) * 0.0625f;
            Wlog[n * 32 + k] = wv;
            *(__half*)(BsmB + n * 144 + k * 2) = __float2half(wv);
        }
    }
    __syncwarp();

    const int j8 = lane >> 3, r8 = lane & 7;
    uint32_t abase = (uint32_t)__cvta_generic_to_shared(AsmB)
                   + (uint32_t)(((j8 & 1) * 8 + r8) * 80 + (j8 >> 1) * 16);
    uint32_t bbase = (uint32_t)__cvta_generic_to_shared(BsmB)
                   + (uint32_t)(r8 * 144 + j8 * 16);
    uint32_t a[4], b[4];
    ldsm_x4(a, abase);
    ldsm_x4(b, bbase);

    const int g = lane >> 2, q = lane & 3;
    float e[4];
    #pragma unroll
    for (int h = 0; h < 4; h++) {
        int r = g + (h >> 1) * 8;
        int n = 2 * q + (h & 1);
        float sum = 0.f;
        for (int k = 0; k < 32; k++) sum += Alog[r * 32 + k] * Wlog[n * 32 + k];
        e[h] = sum;
    }

    const int jpar = lane & 1;
    uint32_t wg = can[g], wg8 = can[g + 8];

    int chosen = NCAND;
    for (int c = 0; c < NCAND; c++) {
        uint32_t E = compose_meta(c, wg, wg8, jpar);
        float d[4] = {0.f, 0.f, 0.f, 0.f};
        if (c >= 5) mma_spp(d, a, b, E);
        else        mma_spo(d, a, b, E);
        bool ok = true;
        #pragma unroll
        for (int h = 0; h < 4; h++) ok &= fabsf(d[h] - e[h]) < 0.01f;
        if (__all_sync(0xFFFFFFFFu, ok) && chosen == NCAND) chosen = c;
    }
    if (lane == 0) { g_flag = chosen; g_ok = 1; }
}

// =====================================================================
// Kernel 1: prune + rescale + canonical meta + meta PRECOMPOSE.
// Blocks 0..2047: 16 rows each. Blocks 2048..2175: weight fp32->fp16.
// =====================================================================
__global__ void __launch_bounds__(512) prep_kernel(const float* __restrict__ x,
                                                   const float* __restrict__ wsrc) {
    const int tid  = threadIdx.x;

    if (blockIdx.x >= 2048) {              // fused weight conversion
        int base = (blockIdx.x - 2048) * 512 + tid;   // 65536 threads
        #pragma unroll
        for (int j = 0; j < 4; j++) {
            int i = base * 4 + j;          // float4 index, 262144 total
            float4 v = reinterpret_cast<const float4*>(wsrc)[i];
            __half2 h0 = __floats2half2_rn(v.x, v.y);
            __half2 h1 = __floats2half2_rn(v.z, v.w);
            uint2 u;
            u.x = *reinterpret_cast<uint32_t*>(&h0);
            u.y = *reinterpret_cast<uint32_t*>(&h1);
            reinterpret_cast<uint2*>(g_wt)[i] = u;
        }
        return;
    }

    __shared__ uint32_t canw[16 * 32];     // canonical words [row_in_block][kw]
    const int wid  = tid >> 5;
    const int lane = tid & 31;
    const int row  = blockIdx.x * 16 + wid;
    const float4* src = reinterpret_cast<const float4*>(x + (size_t)row * 1024);

    float k0v[8], k1v[8];
    int   nib[8];
    float s = 0.f, ss = 0.f, ps = 0.f, pss = 0.f;
    #pragma unroll
    for (int jj = 0; jj < 8; jj++) {
        const float4 g4 = src[lane + 32 * jj];
        float v0 = g4.x, v1 = g4.y, v2 = g4.z, v3 = g4.w;
        float a0 = fabsf(v0), a1 = fabsf(v1), a2 = fabsf(v2), a3 = fabsf(v3);
        int r0 = (a1 >  a0) + (a2 >  a0) + (a3 >  a0);
        int r1 = (a0 >= a1) + (a2 >  a1) + (a3 >  a1);
        int r2 = (a0 >= a2) + (a1 >= a2) + (a3 >  a2);
        int r3 = (a0 >= a3) + (a1 >= a3) + (a2 >= a3);
        bool q0 = r0 < 2, q1 = r1 < 2, q2 = r2 < 2, q3 = r3 < 2;
        int e0 = q0 ? 0 : (q1 ? 1 : 2);
        int e1 = q3 ? 3 : (q2 ? 2 : 1);
        float kv0 = q0 ? v0 : (q1 ? v1 : v2);
        float kv1 = q3 ? v3 : (q2 ? v2 : v1);
        k0v[jj] = kv0; k1v[jj] = kv1;
        nib[jj] = e0 | (e1 << 2);
        s   += v0 + v1 + v2 + v3;
        ss  += v0*v0 + v1*v1 + v2*v2 + v3*v3;
        ps  += kv0 + kv1;
        pss += kv0*kv0 + kv1*kv1;
    }
    #pragma unroll
    for (int off = 16; off; off >>= 1) {
        s   += __shfl_xor_sync(0xFFFFFFFFu, s,   off);
        ss  += __shfl_xor_sync(0xFFFFFFFFu, ss,  off);
        ps  += __shfl_xor_sync(0xFFFFFFFFu, ps,  off);
        pss += __shfl_xor_sync(0xFFFFFFFFu, pss, off);
    }
    float varx = (ss  - s  * s  * (1.f / 1024.f)) * (1.f / 1023.f);
    float varp = (pss - ps * ps * (1.f / 1024.f)) * (1.f / 1023.f);
    varp = fmaxf(varp, 1e-9f);
    const float sc = sqrtf(varx / varp);

    uint32_t* dc = reinterpret_cast<uint32_t*>(g_actc + (size_t)row * 512);
    #pragma unroll
    for (int jj = 0; jj < 8; jj++) {
        __half2 hc = __floats2half2_rn(sc * k0v[jj], sc * k1v[jj]);
        dc[lane + 32 * jj] = *reinterpret_cast<uint32_t*>(&hc);

        uint32_t m = (uint32_t)nib[jj] << (4 * (lane & 7));
        m |= __shfl_xor_sync(0xFFFFFFFFu, m, 1);
        m |= __shfl_xor_sync(0xFFFFFFFFu, m, 2);
        m |= __shfl_xor_sync(0xFFFFFFFFu, m, 4);
        if ((lane & 7) == 0)
            canw[wid * 32 + 4 * jj + (lane >> 3)] = m;
    }
    __syncthreads();

    // canonical words to global (for verify/densify):
    g_can[(size_t)blockIdx.x * 512 + tid] = canw[tid];

    // Compose: each thread emits one final per-thread metadata word.
    // Output layout: g_meta[(mb*32 + kw)*16 + (g*2 + jpar)]
    const int fl   = g_flag;
    const int kw   = tid >> 4;
    const int idx  = tid & 15;
    const int g    = idx >> 1;
    const int jpar = idx & 1;
    uint32_t wg  = canw[g * 32 + kw];
    uint32_t wg8 = canw[(g + 8) * 32 + kw];
    g_meta[((size_t)blockIdx.x * 32 + kw) * 16 + idx] =
        compose_meta(fl, wg, wg8, jpar);
}

// =====================================================================
// Kernel 3a: SPARSE GEMM. CTA 128x128, warp 64x32, 3 stages, 2 CTAs/SM.
// B fragments double-buffered (R13 exact — best measured config).
// =====================================================================
static constexpr int SA_ROWB = 80;
static constexpr int SB_ROWB = 144;
static constexpr int SA_BYTES = 128 * SA_ROWB;   // 10240
static constexpr int SB_BYTES = 128 * SB_ROWB;   // 18432
static constexpr int SOFF_B = SA_BYTES;
static constexpr int SOFF_M = SA_BYTES + SB_BYTES;
static constexpr int SSTAGE = SOFF_M + 1024;     // 29696
static constexpr unsigned SSMEM = 3 * SSTAGE;    // 89088

__global__ void __launch_bounds__(256, 2) gemm_sparse(float* __restrict__ C) {
    const int fl = g_flag;
    if (fl >= NCAND) return;

    extern __shared__ char smem[];
    const int tid  = threadIdx.x;
    const int lane = tid & 31;
    const int w    = tid >> 5;
    const int wm   = w & 1;
    const int wn   = w >> 1;
    const int g    = lane >> 2;
    const int t    = lane & 3;
    const int jpar = lane & 1;

    const int m0 = blockIdx.y * 128;
    const int n0 = blockIdx.x * 128;

    float acc[4][4][4];
    #pragma unroll
    for (int i = 0; i < 4; i++)
        #pragma unroll
        for (int jj = 0; jj < 4; jj++)
            #pragma unroll
            for (int q = 0; q < 4; q++) acc[i][jj][q] = 0.f;

    const __half*   Agb = g_actc + (size_t)m0 * 512;
    const __half*   Bgb = g_wt   + (size_t)n0 * 1024;
    const uint32_t* Mgb = g_meta + (size_t)(m0 >> 4) * 512;

    const uint32_t smem_base = (uint32_t)__cvta_generic_to_shared(smem);
    const int j8 = lane >> 3, r8 = lane & 7;
    const uint32_t a_lane_off =
        (uint32_t)((wm * 64 + (j8 & 1) * 8 + r8) * SA_ROWB + (j8 >> 1) * 16);
    const uint32_t b_lane_off = (uint32_t)(SOFF_B + r8 * SB_ROWB + j8 * 16);
    const uint32_t m_lane_off = (uint32_t)(SOFF_M + (g * 2 + jpar) * 4);

    auto load_stage = [&](int kt, int st_i) {
        char* st = smem + st_i * SSTAGE;
        const __half* Ag = Agb + kt * 32;
        const __half* Bg = Bgb + kt * 64;
        #pragma unroll
        for (int i = 0; i < 2; i++) {
            int ch = tid + i * 256;
            int r = ch >> 2, c = ch & 3;
            cp16(st + r * SA_ROWB + c * 16, Ag + (size_t)r * 512 + c * 8);
        }
        #pragma unroll
        for (int i = 0; i < 4; i++) {
            int ch = tid + i * 256;
            int r = ch >> 3, c = ch & 7;
            cp16(st + SOFF_B + r * SB_ROWB + c * 16, Bg + (size_t)r * 1024 + c * 8);
        }
        if (tid < 64) {
            int mb = tid >> 3, c = tid & 7;
            cp16(st + SOFF_M + mb * 128 + c * 16,
                 Mgb + ((size_t)mb * 32 + kt * 2) * 16 + c * 4);
        }
        cp_commit();
    };

    load_stage(0, 0);
    load_stage(1, 1);

    for (int kt = 0; kt < 16; kt++) {
        cp_wait<1>();
        __syncthreads();

        if (kt + 2 < 16) load_stage(kt + 2, (kt + 2) % 3);

        const uint32_t st = smem_base + (uint32_t)((kt % 3) * SSTAGE);
        #pragma unroll
        for (int kk = 0; kk < 2; kk++) {
            uint32_t E[4];
            #pragma unroll
            for (int mt = 0; mt < 4; mt++)
                E[mt] = lds32(st + m_lane_off
                              + (uint32_t)((wm * 4 + mt) * 128 + kk * 64));
            uint32_t a[4][4];
            #pragma unroll
            for (int mt = 0; mt < 4; mt++)
                ldsm_x4(a[mt], st + a_lane_off + mt * (16 * SA_ROWB) + kk * 32);

            // B fragment double buffer: break the ldsm->mma use chain.
            uint32_t b2[2][4];
            const uint32_t bb = st + b_lane_off + (uint32_t)(wn * 32 * SB_ROWB)
                              + (uint32_t)(kk * 64);
            ldsm_x4(b2[0], bb);
            if (fl >= 5) {
                #pragma unroll
                for (int nt = 0; nt < 4; nt++) {
                    if (nt < 3)
                        ldsm_x4(b2[(nt + 1) & 1], bb + (nt + 1) * 8 * SB_ROWB);
                    #pragma unroll
                    for (int mt = 0; mt < 4; mt++)
                        mma_spp(acc[mt][nt], a[mt], b2[nt & 1], E[mt]);
                }
            } else {
                #pragma unroll
                for (int nt = 0; nt < 4; nt++) {
                    if (nt < 3)
                        ldsm_x4(b2[(nt + 1) & 1], bb + (nt + 1) * 8 * SB_ROWB);
                    #pragma unroll
                    for (int mt = 0; mt < 4; mt++)
                        mma_spo(acc[mt][nt], a[mt], b2[nt & 1], E[mt]);
                }
            }
        }
    }

    #pragma unroll
    for (int mt = 0; mt < 4; mt++) {
        const int row = m0 + wm * 64 + mt * 16 + g;
        #pragma unroll
        for (int nt = 0; nt < 4; nt++) {
            const int col = n0 + wn * 32 + nt * 8 + 2 * t;
            float2 v0 = make_float2(acc[mt][nt][0], acc[mt][nt][1]);
            float2 v1 = make_float2(acc[mt][nt][2], acc[mt][nt][3]);
            *reinterpret_cast<float2*>(&C[(size_t)row * 1024 + col])       = v0;
            *reinterpret_cast<float2*>(&C[(size_t)(row + 8) * 1024 + col]) = v1;
        }
    }
}

// =====================================================================
// Kernel 4: verify (slim). 128 blocks = 16 rows x 8 n-chunks; 16 cols
// per block, offsets vary per row -> all positions mod 16 covered.
// =====================================================================
__global__ void __launch_bounds__(256) verify_kernel(const float* __restrict__ C) {
    if (g_flag >= NCAND) {
        if (blockIdx.x == 0 && threadIdx.x == 0) g_ok = 0;
        return;
    }
    __shared__ __half arow[1024];
    const int tid  = threadIdx.x;
    const int wid  = tid >> 5;
    const int lane = tid & 31;
    const int rsel = blockIdx.x >> 3;
    const int row  = rsel * 2048 + ((rsel * 1337) & 2047);
    const int colbase = (blockIdx.x & 7) * 128;

    {
        uint32_t pair = reinterpret_cast<const uint32_t*>(
                            g_actc + (size_t)row * 512)[tid];
        uint32_t word = g_can[(size_t)row * 32 + (tid >> 3)];
        uint32_t nb = (word >> (4 * (tid & 7))) & 0xFu;
        int e0 = nb & 3, e1 = (nb >> 2) & 3;
        __half2 hv = *reinterpret_cast<__half2*>(&pair);
        __half z = __float2half(0.f);
        __half v[4] = { z, z, z, z };
        v[e0] = __low2half(hv);
        v[e1] = __high2half(hv);
        arow[4 * tid + 0] = v[0];
        arow[4 * tid + 1] = v[1];
        arow[4 * tid + 2] = v[2];
        arow[4 * tid + 3] = v[3];
    }
    __syncthreads();

    const __half2* a2 = reinterpret_cast<const __half2*>(arow);
    #pragma unroll
    for (int c0 = 0; c0 < 2; c0++) {
        const int col = colbase + wid * 16 + c0 * 8 + (rsel & 7);
        const __half2* w2 =
            reinterpret_cast<const __half2*>(g_wt + (size_t)col * 1024);
        float sum = 0.f;
        for (int k = lane; k < 512; k += 32) {
            float2 af = __half22float2(a2[k]);
            float2 wf = __half22float2(w2[k]);
            sum = fmaf(af.x, wf.x, fmaf(af.y, wf.y, sum));
        }
        #pragma unroll
        for (int off = 16; off; off >>= 1)
            sum += __shfl_xor_sync(0xFFFFFFFFu, sum, off);
        if (lane == 0) {
            float got = C[(size_t)row * 1024 + col];
            if (fabsf(got - sum) > 0.02f * (fabsf(sum) + 0.25f)) g_ok = 0;
        }
    }
}

// =====================================================================
// Kernel 5: densify (iff !g_ok). Grid 2048, 16-way interior loop.
// =====================================================================
__global__ void __launch_bounds__(256) densify_kernel() {
    if (g_ok) return;
    #pragma unroll
    for (int i = 0; i < 16; i++) {
        int gi = (blockIdx.x * 16 + i) * 256 + threadIdx.x;
        int row = gi >> 8, gg = gi & 255;
        uint32_t pair = reinterpret_cast<const uint32_t*>(
                            g_actc + (size_t)row * 512)[gg];
        uint32_t word = g_can[(size_t)row * 32 + (gg >> 3)];
        uint32_t nb = (word >> (4 * (gg & 7))) & 0xFu;
        int e0 = nb & 3, e1 = (nb >> 2) & 3;
        __half2 hv = *reinterpret_cast<__half2*>(&pair);
        __half z = __float2half(0.f);
        __half v[4] = { z, z, z, z };
        v[e0] = __low2half(hv);
        v[e1] = __high2half(hv);
        __half2 lo = __halves2half2(v[0], v[1]);
        __half2 hi = __halves2half2(v[2], v[3]);
        uint2 o;
        o.x = *reinterpret_cast<uint32_t*>(&lo);
        o.y = *reinterpret_cast<uint32_t*>(&hi);
        reinterpret_cast<uint2*>(g_actd)[gi] = o;
    }
}

// =====================================================================
// Kernel 3b: DENSE GEMM fallback (iff !g_ok). Proven R5 kernel.
// =====================================================================
static constexpr int DLDH = 40;
static constexpr int DA_ELTS = 128 * DLDH;
static constexpr int DSTAGE_ELTS = 2 * DA_ELTS;
static constexpr unsigned DSMEM = 4 * DSTAGE_ELTS * 2;           // 81920

__global__ void __launch_bounds__(256, 2) gemm_dense(float* __restrict__ C) {
    if (g_ok) return;

    extern __shared__ __half dsm[];
    const int tid  = threadIdx.x;
    const int lane = tid & 31;
    const int w    = tid >> 5;
    const int wm   = w & 1;
    const int wn   = w >> 1;
    const int g    = lane >> 2;
    const int t    = lane & 3;

    const int m0 = blockIdx.y * 128;
    const int n0 = blockIdx.x * 128;

    float acc[4][4][4];
    #pragma unroll
    for (int i = 0; i < 4; i++)
        #pragma unroll
        for (int jj = 0; jj < 4; jj++)
            #pragma unroll
            for (int q = 0; q < 4; q++) acc[i][jj][q] = 0.f;

    const __half* Agb = g_actd + (size_t)m0 * 1024;
    const __half* Bgb = g_wt   + (size_t)n0 * 1024;
    const uint32_t smem_base = (uint32_t)__cvta_generic_to_shared(dsm);

    const int j8 = lane >> 3, r8 = lane & 7;
    const uint32_t a_lane_off =
        (uint32_t)((wm * 64 + (j8 & 1) * 8 + r8) * 80 + (j8 >> 1) * 16);
    const uint32_t b_lane_off =
        (uint32_t)(DA_ELTS * 2 + (wn * 32 + (j8 >> 1) * 8 + r8) * 80 + (j8 & 1) * 16);

    auto load_stage = [&](int kt, int st_i) {
        __half* As = dsm + st_i * DSTAGE_ELTS;
        __half* Bs = As + DA_ELTS;
        const __half* Ag = Agb + kt * 32;
        const __half* Bg = Bgb + kt * 32;
        #pragma unroll
        for (int i = 0; i < 2; i++) {
            int ch = tid + i * 256;
            int r = ch >> 2, c = ch & 3;
            cp16(As + r * DLDH + c * 8, Ag + (size_t)r * 1024 + c * 8);
        }
        #pragma unroll
        for (int i = 0; i < 2; i++) {
            int ch = tid + i * 256;
            int r = ch >> 2, c = ch & 3;
            cp16(Bs + r * DLDH + c * 8, Bg + (size_t)r * 1024 + c * 8);
        }
        cp_commit();
    };

    load_stage(0, 0);
    load_stage(1, 1);
    load_stage(2, 2);

    for (int kt = 0; kt < 32; kt++) {
        cp_wait<2>();
        __syncthreads();

        if (kt + 3 < 32) load_stage(kt + 3, (kt + 3) & 3);

        const uint32_t st = smem_base + (uint32_t)((kt & 3) * DSTAGE_ELTS * 2);
        const uint32_t abase = st + a_lane_off;
        const uint32_t bbase = st + b_lane_off;

        #pragma unroll
        for (int kk = 0; kk < 2; kk++) {
            uint32_t a[4][4];
            #pragma unroll
            for (int mt = 0; mt < 4; mt++)
                ldsm_x4(a[mt], abase + mt * (16 * 80) + kk * 32);
            uint32_t b[2][4];
            #pragma unroll
            for (int np = 0; np < 2; np++)
                ldsm_x4(b[np], bbase + np * (16 * 80) + kk * 32);
            #pragma unroll
            for (int mt = 0; mt < 4; mt++)
                #pragma unroll
                for (int nt = 0; nt < 4; nt++)
                    mma_f16(acc[mt][nt], a[mt], &b[nt >> 1][(nt & 1) * 2]);
        }
    }

    #pragma unroll
    for (int mt = 0; mt < 4; mt++) {
        const int row = m0 + wm * 64 + mt * 16 + g;
        #pragma unroll
        for (int nt = 0; nt < 4; nt++) {
            const int col = n0 + wn * 32 + nt * 8 + 2 * t;
            float2 v0 = make_float2(acc[mt][nt][0], acc[mt][nt][1]);
            float2 v1 = make_float2(acc[mt][nt][2], acc[mt][nt][3]);
            *reinterpret_cast<float2*>(&C[(size_t)row * 1024 + col])       = v0;
            *reinterpret_cast<float2*>(&C[(size_t)(row + 8) * 1024 + col]) = v1;
        }
    }
}

// =====================================================================
// Host launcher
// =====================================================================
extern "C" void kernel_launch(void* const* d_in, const int* in_sizes, int n_in,
                              void* d_out, int out_size) {
    const float* x = (const float*)d_in[0];
    const float* w = (const float*)d_in[1];
    if (n_in >= 2 && in_sizes[0] == 1048576 && in_sizes[1] != 1048576) {
        const float* tswap = x; x = w; w = tswap;
    }
    float* out = (float*)d_out;

    probe_kernel<<<1, 32>>>();
    prep_kernel<<<2176, 512>>>(x, w);     // 2048 act blocks + 128 weight blocks

    cudaFuncSetAttribute(gemm_sparse,
                         cudaFuncAttributeMaxDynamicSharedMemorySize, SSMEM);
    cudaFuncSetAttribute(gemm_dense,
                         cudaFuncAttributeMaxDynamicSharedMemorySize, DSMEM);

    gemm_sparse<<<dim3(8, 256), 256, SSMEM>>>(out);
    verify_kernel<<<128, 256>>>(out);
    densify_kernel<<<2048, 256>>>();
    gemm_dense<<<dim3(8, 256), 256, DSMEM>>>(out);
}

// round 16
// speedup vs baseline: 1.0719x; 1.0007x over previous
#include <cuda_runtime.h>
#include <cuda_fp16.h>
#include <cstdint>

static constexpr int NCAND = 7;

// =====================================================================
// Device scratch (allocation-free: __device__ globals)
// =====================================================================
__device__ int      g_flag;            // chosen metadata layout, NCAND = none
__device__ int      g_ok;              // sparse result verified?
__device__ __half   g_actc[16777216];  // 32768 x 512 compressed 2:4 fp16
__device__ uint32_t g_meta[1048576];   // PRECOMPOSED meta: [mb][kw][16]
__device__ uint32_t g_can[1048576];    // canonical meta words [row][kw]
__device__ __half   g_actd[33554432];  // dense fp16 (built only on fallback)
__device__ __half   g_wt[1048576];     // 1024 x 1024 fp16 weight

// =====================================================================
// Helpers (base ISA only)
// =====================================================================
__device__ __forceinline__ void cp16(void* s, const void* g) {
    uint32_t sa = (uint32_t)__cvta_generic_to_shared(s);
    asm volatile("cp.async.cg.shared.global [%0], [%1], 16;"
                 :: "r"(sa), "l"(g) : "memory");
}
__device__ __forceinline__ void cp_commit() {
    asm volatile("cp.async.commit_group;" ::: "memory");
}
template <int N>
__device__ __forceinline__ void cp_wait() {
    asm volatile("cp.async.wait_group %0;" :: "n"(N) : "memory");
}
__device__ __forceinline__ void ldsm_x4(uint32_t* r, uint32_t addr) {
    asm volatile("ldmatrix.sync.aligned.m8n8.x4.shared.b16 {%0,%1,%2,%3}, [%4];"
                 : "=r"(r[0]), "=r"(r[1]), "=r"(r[2]), "=r"(r[3]) : "r"(addr));
}
__device__ __forceinline__ uint32_t lds32(uint32_t addr) {
    uint32_t v;
    asm volatile("ld.shared.u32 %0, [%1];" : "=r"(v) : "r"(addr));
    return v;
}
__device__ __forceinline__ void mma_f16(float* d, const uint32_t* a,
                                        const uint32_t* b) {
    asm volatile(
        "mma.sync.aligned.m16n8k16.row.col.f32.f16.f16.f32 "
        "{%0,%1,%2,%3}, {%4,%5,%6,%7}, {%8,%9}, {%0,%1,%2,%3};"
        : "+f"(d[0]), "+f"(d[1]), "+f"(d[2]), "+f"(d[3])
        : "r"(a[0]), "r"(a[1]), "r"(a[2]), "r"(a[3]), "r"(b[0]), "r"(b[1]));
}
__device__ __forceinline__ void mma_spo(float* d, const uint32_t* a,
                                        const uint32_t* b, uint32_t e) {
    asm volatile(
        "mma.sp::ordered_metadata.sync.aligned.m16n8k32.row.col.f32.f16.f16.f32 "
        "{%0,%1,%2,%3}, {%4,%5,%6,%7}, {%8,%9,%10,%11}, {%0,%1,%2,%3}, %12, 0x0;"
        : "+f"(d[0]), "+f"(d[1]), "+f"(d[2]), "+f"(d[3])
        : "r"(a[0]), "r"(a[1]), "r"(a[2]), "r"(a[3]),
          "r"(b[0]), "r"(b[1]), "r"(b[2]), "r"(b[3]), "r"(e));
}
__device__ __forceinline__ void mma_spp(float* d, const uint32_t* a,
                                        const uint32_t* b, uint32_t e) {
    asm volatile(
        "mma.sp.sync.aligned.m16n8k32.row.col.f32.f16.f16.f32 "
        "{%0,%1,%2,%3}, {%4,%5,%6,%7}, {%8,%9,%10,%11}, {%0,%1,%2,%3}, %12, 0x0;"
        : "+f"(d[0]), "+f"(d[1]), "+f"(d[2]), "+f"(d[3])
        : "r"(a[0]), "r"(a[1]), "r"(a[2]), "r"(a[3]),
          "r"(b[0]), "r"(b[1]), "r"(b[2]), "r"(b[3]), "r"(e));
}

__device__ __forceinline__ uint32_t nibble_ilv(uint32_t x, uint32_t y) {
    return (x & 0xFu) | ((y & 0xFu) << 4) | ((x & 0xF0u) << 4) | ((y & 0xF0u) << 8)
         | ((x & 0xF00u) << 8) | ((y & 0xF00u) << 12)
         | ((x & 0xF000u) << 12) | ((y & 0xF000u) << 16);
}
__device__ __forceinline__ uint32_t compose_meta(int fl, uint32_t wg,
                                                 uint32_t wg8, int jpar) {
    uint32_t x = (wg  >> (16 * jpar)) & 0xFFFFu;
    uint32_t y = (wg8 >> (16 * jpar)) & 0xFFFFu;
    switch (fl) {
        case 0: return x | (y << 16);        // ordered, half-split
        case 1: return nibble_ilv(x, y);     // ordered, nibble-interleave
        case 2: return jpar ? wg8 : wg;      // ordered, P0
        case 3: return jpar ? wg : wg8;      // ordered, P0 swapped
        case 4: return y | (x << 16);        // ordered, half-split swapped
        case 5: return jpar ? wg8 : wg;      // plain mma.sp, P0
        case 6: return x | (y << 16);        // plain mma.sp, half-split
    }
    return 0;
}

// =====================================================================
// Probe: ISA-level metadata layout discovery (register-fed metadata).
// =====================================================================
__global__ void probe_kernel() {
    __shared__ char     AsmB[16 * 80];
    __shared__ char     BsmB[8 * 144];
    __shared__ uint32_t can[16];
    __shared__ float    Alog[16 * 32];
    __shared__ float    Wlog[8 * 32];

    const int lane = threadIdx.x & 31;

    for (int i = lane; i < 16 * 80 / 4; i += 32) ((uint32_t*)AsmB)[i] = 0;
    for (int i = lane; i < 16 * 32; i += 32) Alog[i] = 0.f;
    __syncwarp();

    if (lane < 16) {
        const int r = lane;
        const int pe0[6] = {0, 0, 0, 1, 1, 2};
        const int pe1[6] = {1, 2, 3, 2, 3, 3};
        uint32_t word = 0;
        for (int gg = 0; gg < 8; gg++) {
            int p  = (r * 8 + gg) % 6;
            int e0 = pe0[p], e1 = pe1[p];
            word |= (uint32_t)(e0 | (e1 << 2)) << (4 * gg);
            int k0 = 4 * gg + e0, k1 = 4 * gg + e1;
            float v0 = ((float)((r * 32 + k0) % 19) - 9.f) * 0.125f;
            float v1 = ((float)((r * 32 + k1) % 19) - 9.f) * 0.125f;
            Alog[r * 32 + k0] = v0;
            Alog[r * 32 + k1] = v1;
            *(__half*)(AsmB + r * 80 + (2 * gg + 0) * 2) = __float2half(v0);
            *(__half*)(AsmB + r * 80 + (2 * gg + 1) * 2) = __float2half(v1);
        }
        can[r] = word;
    }
    if (lane < 8) {
        const int n = lane;
        for (int k = 0; k < 32; k++) {
            float wv = ((float)((k * 8 + n) % 23) - 11.f) * 0.0625f;
            Wlog[n * 32 + k] = wv;
            *(__half*)(BsmB + n * 144 + k * 2) = __float2half(wv);
        }
    }
    __syncwarp();

    const int j8 = lane >> 3, r8 = lane & 7;
    uint32_t abase = (uint32_t)__cvta_generic_to_shared(AsmB)
                   + (uint32_t)(((j8 & 1) * 8 + r8) * 80 + (j8 >> 1) * 16);
    uint32_t bbase = (uint32_t)__cvta_generic_to_shared(BsmB)
                   + (uint32_t)(r8 * 144 + j8 * 16);
    uint32_t a[4], b[4];
    ldsm_x4(a, abase);
    ldsm_x4(b, bbase);

    const int g = lane >> 2, q = lane & 3;
    float e[4];
    #pragma unroll
    for (int h = 0; h < 4; h++) {
        int r = g + (h >> 1) * 8;
        int n = 2 * q + (h & 1);
        float sum = 0.f;
        for (int k = 0; k < 32; k++) sum += Alog[r * 32 + k] * Wlog[n * 32 + k];
        e[h] = sum;
    }

    const int jpar = lane & 1;
    uint32_t wg = can[g], wg8 = can[g + 8];

    int chosen = NCAND;
    for (int c = 0; c < NCAND; c++) {
        uint32_t E = compose_meta(c, wg, wg8, jpar);
        float d[4] = {0.f, 0.f, 0.f, 0.f};
        if (c >= 5) mma_spp(d, a, b, E);
        else        mma_spo(d, a, b, E);
        bool ok = true;
        #pragma unroll
        for (int h = 0; h < 4; h++) ok &= fabsf(d[h] - e[h]) < 0.01f;
        if (__all_sync(0xFFFFFFFFu, ok) && chosen == NCAND) chosen = c;
    }
    if (lane == 0) { g_flag = chosen; g_ok = 1; }
}

// =====================================================================
// Kernel 1: prune + rescale + canonical meta + meta PRECOMPOSE.
// Blocks 0..2047: 16 rows each. Blocks 2048..2175: weight fp32->fp16.
// =====================================================================
__global__ void __launch_bounds__(512) prep_kernel(const float* __restrict__ x,
                                                   const float* __restrict__ wsrc) {
    const int tid  = threadIdx.x;

    if (blockIdx.x >= 2048) {              // fused weight conversion
        int base = (blockIdx.x - 2048) * 512 + tid;   // 65536 threads
        #pragma unroll
        for (int j = 0; j < 4; j++) {
            int i = base * 4 + j;          // float4 index, 262144 total
            float4 v = reinterpret_cast<const float4*>(wsrc)[i];
            __half2 h0 = __floats2half2_rn(v.x, v.y);
            __half2 h1 = __floats2half2_rn(v.z, v.w);
            uint2 u;
            u.x = *reinterpret_cast<uint32_t*>(&h0);
            u.y = *reinterpret_cast<uint32_t*>(&h1);
            reinterpret_cast<uint2*>(g_wt)[i] = u;
        }
        return;
    }

    __shared__ uint32_t canw[16 * 32];     // canonical words [row_in_block][kw]
    const int wid  = tid >> 5;
    const int lane = tid & 31;
    const int row  = blockIdx.x * 16 + wid;
    const float4* src = reinterpret_cast<const float4*>(x + (size_t)row * 1024);

    float k0v[8], k1v[8];
    int   nib[8];
    float s = 0.f, ss = 0.f, ps = 0.f, pss = 0.f;
    #pragma unroll
    for (int jj = 0; jj < 8; jj++) {
        const float4 g4 = src[lane + 32 * jj];
        float v0 = g4.x, v1 = g4.y, v2 = g4.z, v3 = g4.w;
        float a0 = fabsf(v0), a1 = fabsf(v1), a2 = fabsf(v2), a3 = fabsf(v3);
        int r0 = (a1 >  a0) + (a2 >  a0) + (a3 >  a0);
        int r1 = (a0 >= a1) + (a2 >  a1) + (a3 >  a1);
        int r2 = (a0 >= a2) + (a1 >= a2) + (a3 >  a2);
        int r3 = (a0 >= a3) + (a1 >= a3) + (a2 >= a3);
        bool q0 = r0 < 2, q1 = r1 < 2, q2 = r2 < 2, q3 = r3 < 2;
        int e0 = q0 ? 0 : (q1 ? 1 : 2);
        int e1 = q3 ? 3 : (q2 ? 2 : 1);
        float kv0 = q0 ? v0 : (q1 ? v1 : v2);
        float kv1 = q3 ? v3 : (q2 ? v2 : v1);
        k0v[jj] = kv0; k1v[jj] = kv1;
        nib[jj] = e0 | (e1 << 2);
        s   += v0 + v1 + v2 + v3;
        ss  += v0*v0 + v1*v1 + v2*v2 + v3*v3;
        ps  += kv0 + kv1;
        pss += kv0*kv0 + kv1*kv1;
    }
    #pragma unroll
    for (int off = 16; off; off >>= 1) {
        s   += __shfl_xor_sync(0xFFFFFFFFu, s,   off);
        ss  += __shfl_xor_sync(0xFFFFFFFFu, ss,  off);
        ps  += __shfl_xor_sync(0xFFFFFFFFu, ps,  off);
        pss += __shfl_xor_sync(0xFFFFFFFFu, pss, off);
    }
    float varx = (ss  - s  * s  * (1.f / 1024.f)) * (1.f / 1023.f);
    float varp = (pss - ps * ps * (1.f / 1024.f)) * (1.f / 1023.f);
    varp = fmaxf(varp, 1e-9f);
    const float sc = sqrtf(varx / varp);

    uint32_t* dc = reinterpret_cast<uint32_t*>(g_actc + (size_t)row * 512);
    #pragma unroll
    for (int jj = 0; jj < 8; jj++) {
        __half2 hc = __floats2half2_rn(sc * k0v[jj], sc * k1v[jj]);
        dc[lane + 32 * jj] = *reinterpret_cast<uint32_t*>(&hc);

        uint32_t m = (uint32_t)nib[jj] << (4 * (lane & 7));
        m |= __shfl_xor_sync(0xFFFFFFFFu, m, 1);
        m |= __shfl_xor_sync(0xFFFFFFFFu, m, 2);
        m |= __shfl_xor_sync(0xFFFFFFFFu, m, 4);
        if ((lane & 7) == 0)
            canw[wid * 32 + 4 * jj + (lane >> 3)] = m;
    }
    __syncthreads();

    // canonical words to global (for verify/densify):
    g_can[(size_t)blockIdx.x * 512 + tid] = canw[tid];

    // Compose: each thread emits one final per-thread metadata word.
    // Output layout: g_meta[(mb*32 + kw)*16 + (g*2 + jpar)]
    const int fl   = g_flag;
    const int kw   = tid >> 4;
    const int idx  = tid & 15;
    const int g    = idx >> 1;
    const int jpar = idx & 1;
    uint32_t wg  = canw[g * 32 + kw];
    uint32_t wg8 = canw[(g + 8) * 32 + kw];
    g_meta[((size_t)blockIdx.x * 32 + kw) * 16 + idx] =
        compose_meta(fl, wg, wg8, jpar);
}

// =====================================================================
// Kernel 3a: SPARSE GEMM. CTA 128x128, warp 64x32, 3 stages, 2 CTAs/SM.
// B fragments double-buffered (R13/R15 exact — best measured config).
// =====================================================================
static constexpr int SA_ROWB = 80;
static constexpr int SB_ROWB = 144;
static constexpr int SA_BYTES = 128 * SA_ROWB;   // 10240
static constexpr int SB_BYTES = 128 * SB_ROWB;   // 18432
static constexpr int SOFF_B = SA_BYTES;
static constexpr int SOFF_M = SA_BYTES + SB_BYTES;
static constexpr int SSTAGE = SOFF_M + 1024;     // 29696
static constexpr unsigned SSMEM = 3 * SSTAGE;    // 89088

__global__ void __launch_bounds__(256, 2) gemm_sparse(float* __restrict__ C) {
    const int fl = g_flag;
    if (fl >= NCAND) return;

    extern __shared__ char smem[];
    const int tid  = threadIdx.x;
    const int lane = tid & 31;
    const int w    = tid >> 5;
    const int wm   = w & 1;
    const int wn   = w >> 1;
    const int g    = lane >> 2;
    const int t    = lane & 3;
    const int jpar = lane & 1;

    const int m0 = blockIdx.y * 128;
    const int n0 = blockIdx.x * 128;

    float acc[4][4][4];
    #pragma unroll
    for (int i = 0; i < 4; i++)
        #pragma unroll
        for (int jj = 0; jj < 4; jj++)
            #pragma unroll
            for (int q = 0; q < 4; q++) acc[i][jj][q] = 0.f;

    const __half*   Agb = g_actc + (size_t)m0 * 512;
    const __half*   Bgb = g_wt   + (size_t)n0 * 1024;
    const uint32_t* Mgb = g_meta + (size_t)(m0 >> 4) * 512;

    const uint32_t smem_base = (uint32_t)__cvta_generic_to_shared(smem);
    const int j8 = lane >> 3, r8 = lane & 7;
    const uint32_t a_lane_off =
        (uint32_t)((wm * 64 + (j8 & 1) * 8 + r8) * SA_ROWB + (j8 >> 1) * 16);
    const uint32_t b_lane_off = (uint32_t)(SOFF_B + r8 * SB_ROWB + j8 * 16);
    const uint32_t m_lane_off = (uint32_t)(SOFF_M + (g * 2 + jpar) * 4);

    auto load_stage = [&](int kt, int st_i) {
        char* st = smem + st_i * SSTAGE;
        const __half* Ag = Agb + kt * 32;
        const __half* Bg = Bgb + kt * 64;
        #pragma unroll
        for (int i = 0; i < 2; i++) {
            int ch = tid + i * 256;
            int r = ch >> 2, c = ch & 3;
            cp16(st + r * SA_ROWB + c * 16, Ag + (size_t)r * 512 + c * 8);
        }
        #pragma unroll
        for (int i = 0; i < 4; i++) {
            int ch = tid + i * 256;
            int r = ch >> 3, c = ch & 7;
            cp16(st + SOFF_B + r * SB_ROWB + c * 16, Bg + (size_t)r * 1024 + c * 8);
        }
        if (tid < 64) {
            int mb = tid >> 3, c = tid & 7;
            cp16(st + SOFF_M + mb * 128 + c * 16,
                 Mgb + ((size_t)mb * 32 + kt * 2) * 16 + c * 4);
        }
        cp_commit();
    };

    load_stage(0, 0);
    load_stage(1, 1);

    for (int kt = 0; kt < 16; kt++) {
        cp_wait<1>();
        __syncthreads();

        if (kt + 2 < 16) load_stage(kt + 2, (kt + 2) % 3);

        const uint32_t st = smem_base + (uint32_t)((kt % 3) * SSTAGE);
        #pragma unroll
        for (int kk = 0; kk < 2; kk++) {
            uint32_t E[4];
            #pragma unroll
            for (int mt = 0; mt < 4; mt++)
                E[mt] = lds32(st + m_lane_off
                              + (uint32_t)((wm * 4 + mt) * 128 + kk * 64));
            uint32_t a[4][4];
            #pragma unroll
            for (int mt = 0; mt < 4; mt++)
                ldsm_x4(a[mt], st + a_lane_off + mt * (16 * SA_ROWB) + kk * 32);

            // B fragment double buffer: break the ldsm->mma use chain.
            uint32_t b2[2][4];
            const uint32_t bb = st + b_lane_off + (uint32_t)(wn * 32 * SB_ROWB)
                              + (uint32_t)(kk * 64);
            ldsm_x4(b2[0], bb);
            if (fl >= 5) {
                #pragma unroll
                for (int nt = 0; nt < 4; nt++) {
                    if (nt < 3)
                        ldsm_x4(b2[(nt + 1) & 1], bb + (nt + 1) * 8 * SB_ROWB);
                    #pragma unroll
                    for (int mt = 0; mt < 4; mt++)
                        mma_spp(acc[mt][nt], a[mt], b2[nt & 1], E[mt]);
                }
            } else {
                #pragma unroll
                for (int nt = 0; nt < 4; nt++) {
                    if (nt < 3)
                        ldsm_x4(b2[(nt + 1) & 1], bb + (nt + 1) * 8 * SB_ROWB);
                    #pragma unroll
                    for (int mt = 0; mt < 4; mt++)
                        mma_spo(acc[mt][nt], a[mt], b2[nt & 1], E[mt]);
                }
            }
        }
    }

    #pragma unroll
    for (int mt = 0; mt < 4; mt++) {
        const int row = m0 + wm * 64 + mt * 16 + g;
        #pragma unroll
        for (int nt = 0; nt < 4; nt++) {
            const int col = n0 + wn * 32 + nt * 8 + 2 * t;
            float2 v0 = make_float2(acc[mt][nt][0], acc[mt][nt][1]);
            float2 v1 = make_float2(acc[mt][nt][2], acc[mt][nt][3]);
            *reinterpret_cast<float2*>(&C[(size_t)row * 1024 + col])       = v0;
            *reinterpret_cast<float2*>(&C[(size_t)(row + 8) * 1024 + col]) = v1;
        }
    }
}

// =====================================================================
// Kernel 4: verify (slim). 128 blocks = 16 rows x 8 n-chunks; 16 cols
// per block, offsets vary per row -> all positions mod 16 covered.
// =====================================================================
__global__ void __launch_bounds__(256) verify_kernel(const float* __restrict__ C) {
    if (g_flag >= NCAND) {
        if (blockIdx.x == 0 && threadIdx.x == 0) g_ok = 0;
        return;
    }
    __shared__ __half arow[1024];
    const int tid  = threadIdx.x;
    const int wid  = tid >> 5;
    const int lane = tid & 31;
    const int rsel = blockIdx.x >> 3;
    const int row  = rsel * 2048 + ((rsel * 1337) & 2047);
    const int colbase = (blockIdx.x & 7) * 128;

    {
        uint32_t pair = reinterpret_cast<const uint32_t*>(
                            g_actc + (size_t)row * 512)[tid];
        uint32_t word = g_can[(size_t)row * 32 + (tid >> 3)];
        uint32_t nb = (word >> (4 * (tid & 7))) & 0xFu;
        int e0 = nb & 3, e1 = (nb >> 2) & 3;
        __half2 hv = *reinterpret_cast<__half2*>(&pair);
        __half z = __float2half(0.f);
        __half v[4] = { z, z, z, z };
        v[e0] = __low2half(hv);
        v[e1] = __high2half(hv);
        arow[4 * tid + 0] = v[0];
        arow[4 * tid + 1] = v[1];
        arow[4 * tid + 2] = v[2];
        arow[4 * tid + 3] = v[3];
    }
    __syncthreads();

    const __half2* a2 = reinterpret_cast<const __half2*>(arow);
    #pragma unroll
    for (int c0 = 0; c0 < 2; c0++) {
        const int col = colbase + wid * 16 + c0 * 8 + (rsel & 7);
        const __half2* w2 =
            reinterpret_cast<const __half2*>(g_wt + (size_t)col * 1024);
        float sum = 0.f;
        for (int k = lane; k < 512; k += 32) {
            float2 af = __half22float2(a2[k]);
            float2 wf = __half22float2(w2[k]);
            sum = fmaf(af.x, wf.x, fmaf(af.y, wf.y, sum));
        }
        #pragma unroll
        for (int off = 16; off; off >>= 1)
            sum += __shfl_xor_sync(0xFFFFFFFFu, sum, off);
        if (lane == 0) {
            float got = C[(size_t)row * 1024 + col];
            if (fabsf(got - sum) > 0.02f * (fabsf(sum) + 0.25f)) g_ok = 0;
        }
    }
}

// =====================================================================
// Kernel 5: densify (iff !g_ok). PERSISTENT: 148 blocks, strided loop.
// =====================================================================
__global__ void __launch_bounds__(256) densify_kernel() {
    if (g_ok) return;
    // 8388608 groups total; each block handles a strided range.
    for (int base = blockIdx.x; base < 32768; base += 148) {
        int gi = base * 256 + threadIdx.x;
        int row = gi >> 8, gg = gi & 255;
        uint32_t pair = reinterpret_cast<const uint32_t*>(
                            g_actc + (size_t)row * 512)[gg];
        uint32_t word = g_can[(size_t)row * 32 + (gg >> 3)];
        uint32_t nb = (word >> (4 * (gg & 7))) & 0xFu;
        int e0 = nb & 3, e1 = (nb >> 2) & 3;
        __half2 hv = *reinterpret_cast<__half2*>(&pair);
        __half z = __float2half(0.f);
        __half v[4] = { z, z, z, z };
        v[e0] = __low2half(hv);
        v[e1] = __high2half(hv);
        __half2 lo = __halves2half2(v[0], v[1]);
        __half2 hi = __halves2half2(v[2], v[3]);
        uint2 o;
        o.x = *reinterpret_cast<uint32_t*>(&lo);
        o.y = *reinterpret_cast<uint32_t*>(&hi);
        reinterpret_cast<uint2*>(g_actd)[gi] = o;
    }
}

// =====================================================================
// Kernel 3b: DENSE GEMM fallback (iff !g_ok). PERSISTENT: 148 blocks,
// each loops over its share of the 2048 output tiles.
// =====================================================================
static constexpr int DLDH = 40;
static constexpr int DA_ELTS = 128 * DLDH;
static constexpr int DSTAGE_ELTS = 2 * DA_ELTS;
static constexpr unsigned DSMEM = 4 * DSTAGE_ELTS * 2;           // 81920

__global__ void __launch_bounds__(256, 2) gemm_dense(float* __restrict__ C) {
    if (g_ok) return;

    extern __shared__ __half dsm[];
    const int tid  = threadIdx.x;
    const int lane = tid & 31;
    const int w    = tid >> 5;
    const int wm   = w & 1;
    const int wn   = w >> 1;
    const int g    = lane >> 2;
    const int t    = lane & 3;

    const uint32_t smem_base = (uint32_t)__cvta_generic_to_shared(dsm);
    const int j8 = lane >> 3, r8 = lane & 7;
    const uint32_t a_lane_off =
        (uint32_t)((wm * 64 + (j8 & 1) * 8 + r8) * 80 + (j8 >> 1) * 16);
    const uint32_t b_lane_off =
        (uint32_t)(DA_ELTS * 2 + (wn * 32 + (j8 >> 1) * 8 + r8) * 80 + (j8 & 1) * 16);

    for (int tile = blockIdx.x; tile < 2048; tile += 296) {
        const int m0 = (tile >> 3) * 128;
        const int n0 = (tile & 7) * 128;

        float acc[4][4][4];
        #pragma unroll
        for (int i = 0; i < 4; i++)
            #pragma unroll
            for (int jj = 0; jj < 4; jj++)
                #pragma unroll
                for (int q = 0; q < 4; q++) acc[i][jj][q] = 0.f;

        const __half* Agb = g_actd + (size_t)m0 * 1024;
        const __half* Bgb = g_wt   + (size_t)n0 * 1024;

        auto load_stage = [&](int kt, int st_i) {
            __half* As = dsm + st_i * DSTAGE_ELTS;
            __half* Bs = As + DA_ELTS;
            const __half* Ag = Agb + kt * 32;
            const __half* Bg = Bgb + kt * 32;
            #pragma unroll
            for (int i = 0; i < 2; i++) {
                int ch = tid + i * 256;
                int r = ch >> 2, c = ch & 3;
                cp16(As + r * DLDH + c * 8, Ag + (size_t)r * 1024 + c * 8);
            }
            #pragma unroll
            for (int i = 0; i < 2; i++) {
                int ch = tid + i * 256;
                int r = ch >> 2, c = ch & 3;
                cp16(Bs + r * DLDH + c * 8, Bg + (size_t)r * 1024 + c * 8);
            }
            cp_commit();
        };

        load_stage(0, 0);
        load_stage(1, 1);
        load_stage(2, 2);

        for (int kt = 0; kt < 32; kt++) {
            cp_wait<2>();
            __syncthreads();

            if (kt + 3 < 32) load_stage(kt + 3, (kt + 3) & 3);

            const uint32_t st = smem_base + (uint32_t)((kt & 3) * DSTAGE_ELTS * 2);
            const uint32_t abase = st + a_lane_off;
            const uint32_t bbase = st + b_lane_off;

            #pragma unroll
            for (int kk = 0; kk < 2; kk++) {
                uint32_t a[4][4];
                #pragma unroll
                for (int mt = 0; mt < 4; mt++)
                    ldsm_x4(a[mt], abase + mt * (16 * 80) + kk * 32);
                uint32_t b[2][4];
                #pragma unroll
                for (int np = 0; np < 2; np++)
                    ldsm_x4(b[np], bbase + np * (16 * 80) + kk * 32);
                #pragma unroll
                for (int mt = 0; mt < 4; mt++)
                    #pragma unroll
                    for (int nt = 0; nt < 4; nt++)
                        mma_f16(acc[mt][nt], a[mt], &b[nt >> 1][(nt & 1) * 2]);
            }
        }

        #pragma unroll
        for (int mt = 0; mt < 4; mt++) {
            const int row = m0 + wm * 64 + mt * 16 + g;
            #pragma unroll
            for (int nt = 0; nt < 4; nt++) {
                const int col = n0 + wn * 32 + nt * 8 + 2 * t;
                float2 v0 = make_float2(acc[mt][nt][0], acc[mt][nt][1]);
                float2 v1 = make_float2(acc[mt][nt][2], acc[mt][nt][3]);
                *reinterpret_cast<float2*>(&C[(size_t)row * 1024 + col])       = v0;
                *reinterpret_cast<float2*>(&C[(size_t)(row + 8) * 1024 + col]) = v1;
            }
        }

        // drain pipeline + smem reuse barrier before next tile
        cp_wait<0>();
        __syncthreads();
    }
}

// =====================================================================
// Host launcher
// =====================================================================
extern "C" void kernel_launch(void* const* d_in, const int* in_sizes, int n_in,
                              void* d_out, int out_size) {
    const float* x = (const float*)d_in[0];
    const float* w = (const float*)d_in[1];
    if (n_in >= 2 && in_sizes[0] == 1048576 && in_sizes[1] != 1048576) {
        const float* tswap = x; x = w; w = tswap;
    }
    float* out = (float*)d_out;

    probe_kernel<<<1, 32>>>();
    prep_kernel<<<2176, 512>>>(x, w);     // 2048 act blocks + 128 weight blocks

    cudaFuncSetAttribute(gemm_sparse,
                         cudaFuncAttributeMaxDynamicSharedMemorySize, SSMEM);
    cudaFuncSetAttribute(gemm_dense,
                         cudaFuncAttributeMaxDynamicSharedMemorySize, DSMEM);

    gemm_sparse<<<dim3(8, 256), 256, SSMEM>>>(out);
    verify_kernel<<<128, 256>>>(out);
    densify_kernel<<<148, 256>>>();
    gemm_dense<<<296, 256, DSMEM>>>(out);   // persistent: 2 CTAs/SM worth
}

// round 17
// speedup vs baseline: 1.0799x; 1.0075x over previous
#include <cuda_runtime.h>
#include <cuda_fp16.h>
#include <cstdint>

static constexpr int NCAND = 7;

// =====================================================================
// Device scratch (allocation-free: __device__ globals)
// =====================================================================
__device__ int      g_flag;            // chosen metadata layout, NCAND = none
__device__ int      g_ok;              // sparse result verified?
__device__ __half   g_actc[16777216];  // 32768 x 512 compressed 2:4 fp16
__device__ uint32_t g_meta[1048576];   // PRECOMPOSED meta: [mb][kw][16]
__device__ uint32_t g_can[1048576];    // canonical meta words [row][kw]
__device__ __half   g_actd[33554432];  // dense fp16 (built only on fallback)
__device__ __half   g_wt[1048576];     // 1024 x 1024 fp16 weight

// =====================================================================
// Helpers (base ISA only)
// =====================================================================
__device__ __forceinline__ void cp16(void* s, const void* g) {
    uint32_t sa = (uint32_t)__cvta_generic_to_shared(s);
    asm volatile("cp.async.cg.shared.global [%0], [%1], 16;"
                 :: "r"(sa), "l"(g) : "memory");
}
__device__ __forceinline__ void cp_commit() {
    asm volatile("cp.async.commit_group;" ::: "memory");
}
template <int N>
__device__ __forceinline__ void cp_wait() {
    asm volatile("cp.async.wait_group %0;" :: "n"(N) : "memory");
}
__device__ __forceinline__ void ldsm_x4(uint32_t* r, uint32_t addr) {
    asm volatile("ldmatrix.sync.aligned.m8n8.x4.shared.b16 {%0,%1,%2,%3}, [%4];"
                 : "=r"(r[0]), "=r"(r[1]), "=r"(r[2]), "=r"(r[3]) : "r"(addr));
}
__device__ __forceinline__ uint32_t lds32(uint32_t addr) {
    uint32_t v;
    asm volatile("ld.shared.u32 %0, [%1];" : "=r"(v) : "r"(addr));
    return v;
}
__device__ __forceinline__ void mma_f16(float* d, const uint32_t* a,
                                        const uint32_t* b) {
    asm volatile(
        "mma.sync.aligned.m16n8k16.row.col.f32.f16.f16.f32 "
        "{%0,%1,%2,%3}, {%4,%5,%6,%7}, {%8,%9}, {%0,%1,%2,%3};"
        : "+f"(d[0]), "+f"(d[1]), "+f"(d[2]), "+f"(d[3])
        : "r"(a[0]), "r"(a[1]), "r"(a[2]), "r"(a[3]), "r"(b[0]), "r"(b[1]));
}
__device__ __forceinline__ void mma_spo(float* d, const uint32_t* a,
                                        const uint32_t* b, uint32_t e) {
    asm volatile(
        "mma.sp::ordered_metadata.sync.aligned.m16n8k32.row.col.f32.f16.f16.f32 "
        "{%0,%1,%2,%3}, {%4,%5,%6,%7}, {%8,%9,%10,%11}, {%0,%1,%2,%3}, %12, 0x0;"
        : "+f"(d[0]), "+f"(d[1]), "+f"(d[2]), "+f"(d[3])
        : "r"(a[0]), "r"(a[1]), "r"(a[2]), "r"(a[3]),
          "r"(b[0]), "r"(b[1]), "r"(b[2]), "r"(b[3]), "r"(e));
}
__device__ __forceinline__ void mma_spp(float* d, const uint32_t* a,
                                        const uint32_t* b, uint32_t e) {
    asm volatile(
        "mma.sp.sync.aligned.m16n8k32.row.col.f32.f16.f16.f32 "
        "{%0,%1,%2,%3}, {%4,%5,%6,%7}, {%8,%9,%10,%11}, {%0,%1,%2,%3}, %12, 0x0;"
        : "+f"(d[0]), "+f"(d[1]), "+f"(d[2]), "+f"(d[3])
        : "r"(a[0]), "r"(a[1]), "r"(a[2]), "r"(a[3]),
          "r"(b[0]), "r"(b[1]), "r"(b[2]), "r"(b[3]), "r"(e));
}

__device__ __forceinline__ uint32_t nibble_ilv(uint32_t x, uint32_t y) {
    return (x & 0xFu) | ((y & 0xFu) << 4) | ((x & 0xF0u) << 4) | ((y & 0xF0u) << 8)
         | ((x & 0xF00u) << 8) | ((y & 0xF00u) << 12)
         | ((x & 0xF000u) << 12) | ((y & 0xF000u) << 16);
}
__device__ __forceinline__ uint32_t compose_meta(int fl, uint32_t wg,
                                                 uint32_t wg8, int jpar) {
    uint32_t x = (wg  >> (16 * jpar)) & 0xFFFFu;
    uint32_t y = (wg8 >> (16 * jpar)) & 0xFFFFu;
    switch (fl) {
        case 0: return x | (y << 16);        // ordered, half-split
        case 1: return nibble_ilv(x, y);     // ordered, nibble-interleave
        case 2: return jpar ? wg8 : wg;      // ordered, P0
        case 3: return jpar ? wg : wg8;      // ordered, P0 swapped
        case 4: return y | (x << 16);        // ordered, half-split swapped
        case 5: return jpar ? wg8 : wg;      // plain mma.sp, P0
        case 6: return x | (y << 16);        // plain mma.sp, half-split
    }
    return 0;
}

// =====================================================================
// Probe: ISA-level metadata layout discovery (register-fed metadata).
// =====================================================================
__global__ void probe_kernel() {
    __shared__ char     AsmB[16 * 80];
    __shared__ char     BsmB[8 * 144];
    __shared__ uint32_t can[16];
    __shared__ float    Alog[16 * 32];
    __shared__ float    Wlog[8 * 32];

    const int lane = threadIdx.x & 31;

    for (int i = lane; i < 16 * 80 / 4; i += 32) ((uint32_t*)AsmB)[i] = 0;
    for (int i = lane; i < 16 * 32; i += 32) Alog[i] = 0.f;
    __syncwarp();

    if (lane < 16) {
        const int r = lane;
        const int pe0[6] = {0, 0, 0, 1, 1, 2};
        const int pe1[6] = {1, 2, 3, 2, 3, 3};
        uint32_t word = 0;
        for (int gg = 0; gg < 8; gg++) {
            int p  = (r * 8 + gg) % 6;
            int e0 = pe0[p], e1 = pe1[p];
            word |= (uint32_t)(e0 | (e1 << 2)) << (4 * gg);
            int k0 = 4 * gg + e0, k1 = 4 * gg + e1;
            float v0 = ((float)((r * 32 + k0) % 19) - 9.f) * 0.125f;
            float v1 = ((float)((r * 32 + k1) % 19) - 9.f) * 0.125f;
            Alog[r * 32 + k0] = v0;
            Alog[r * 32 + k1] = v1;
            *(__half*)(AsmB + r * 80 + (2 * gg + 0) * 2) = __float2half(v0);
            *(__half*)(AsmB + r * 80 + (2 * gg + 1) * 2) = __float2half(v1);
        }
        can[r] = word;
    }
    if (lane < 8) {
        const int n = lane;
        for (int k = 0; k < 32; k++) {
            float wv = ((float)((k * 8 + n) % 23) - 11.f) * 0.0625f;
            Wlog[n * 32 + k] = wv;
            *(__half*)(BsmB + n * 144 + k * 2) = __float2half(wv);
        }
    }
    __syncwarp();

    const int j8 = lane >> 3, r8 = lane & 7;
    uint32_t abase = (uint32_t)__cvta_generic_to_shared(AsmB)
                   + (uint32_t)(((j8 & 1) * 8 + r8) * 80 + (j8 >> 1) * 16);
    uint32_t bbase = (uint32_t)__cvta_generic_to_shared(BsmB)
                   + (uint32_t)(r8 * 144 + j8 * 16);
    uint32_t a[4], b[4];
    ldsm_x4(a, abase);
    ldsm_x4(b, bbase);

    const int g = lane >> 2, q = lane & 3;
    float e[4];
    #pragma unroll
    for (int h = 0; h < 4; h++) {
        int r = g + (h >> 1) * 8;
        int n = 2 * q + (h & 1);
        float sum = 0.f;
        for (int k = 0; k < 32; k++) sum += Alog[r * 32 + k] * Wlog[n * 32 + k];
        e[h] = sum;
    }

    const int jpar = lane & 1;
    uint32_t wg = can[g], wg8 = can[g + 8];

    int chosen = NCAND;
    for (int c = 0; c < NCAND; c++) {
        uint32_t E = compose_meta(c, wg, wg8, jpar);
        float d[4] = {0.f, 0.f, 0.f, 0.f};
        if (c >= 5) mma_spp(d, a, b, E);
        else        mma_spo(d, a, b, E);
        bool ok = true;
        #pragma unroll
        for (int h = 0; h < 4; h++) ok &= fabsf(d[h] - e[h]) < 0.01f;
        if (__all_sync(0xFFFFFFFFu, ok) && chosen == NCAND) chosen = c;
    }
    if (lane == 0) { g_flag = chosen; g_ok = 1; }
}

// =====================================================================
// Kernel 1: prune + rescale + canonical meta + meta PRECOMPOSE.
// Blocks 0..2047: 16 rows each. Blocks 2048..2175: weight fp32->fp16.
// LOAD PHASE BATCHED: all 8 float4 LDGs issued before any compute (MLP=8).
// =====================================================================
__global__ void __launch_bounds__(512) prep_kernel(const float* __restrict__ x,
                                                   const float* __restrict__ wsrc) {
    const int tid  = threadIdx.x;

    if (blockIdx.x >= 2048) {              // fused weight conversion
        int base = (blockIdx.x - 2048) * 512 + tid;   // 65536 threads
        #pragma unroll
        for (int j = 0; j < 4; j++) {
            int i = base * 4 + j;          // float4 index, 262144 total
            float4 v = reinterpret_cast<const float4*>(wsrc)[i];
            __half2 h0 = __floats2half2_rn(v.x, v.y);
            __half2 h1 = __floats2half2_rn(v.z, v.w);
            uint2 u;
            u.x = *reinterpret_cast<uint32_t*>(&h0);
            u.y = *reinterpret_cast<uint32_t*>(&h1);
            reinterpret_cast<uint2*>(g_wt)[i] = u;
        }
        return;
    }

    __shared__ uint32_t canw[16 * 32];     // canonical words [row_in_block][kw]
    const int wid  = tid >> 5;
    const int lane = tid & 31;
    const int row  = blockIdx.x * 16 + wid;
    const float4* src = reinterpret_cast<const float4*>(x + (size_t)row * 1024);

    // ---- PHASE 1: batched loads (8 independent LDG.128 in flight) ----
    float4 gv[8];
    #pragma unroll
    for (int jj = 0; jj < 8; jj++)
        gv[jj] = src[lane + 32 * jj];

    // ---- PHASE 2: prune + stats ----
    float k0v[8], k1v[8];
    int   nib[8];
    float s = 0.f, ss = 0.f, ps = 0.f, pss = 0.f;
    #pragma unroll
    for (int jj = 0; jj < 8; jj++) {
        float v0 = gv[jj].x, v1 = gv[jj].y, v2 = gv[jj].z, v3 = gv[jj].w;
        float a0 = fabsf(v0), a1 = fabsf(v1), a2 = fabsf(v2), a3 = fabsf(v3);
        int r0 = (a1 >  a0) + (a2 >  a0) + (a3 >  a0);
        int r1 = (a0 >= a1) + (a2 >  a1) + (a3 >  a1);
        int r2 = (a0 >= a2) + (a1 >= a2) + (a3 >  a2);
        int r3 = (a0 >= a3) + (a1 >= a3) + (a2 >= a3);
        bool q0 = r0 < 2, q1 = r1 < 2, q2 = r2 < 2, q3 = r3 < 2;
        int e0 = q0 ? 0 : (q1 ? 1 : 2);
        int e1 = q3 ? 3 : (q2 ? 2 : 1);
        float kv0 = q0 ? v0 : (q1 ? v1 : v2);
        float kv1 = q3 ? v3 : (q2 ? v2 : v1);
        k0v[jj] = kv0; k1v[jj] = kv1;
        nib[jj] = e0 | (e1 << 2);
        s   += v0 + v1 + v2 + v3;
        ss  += v0*v0 + v1*v1 + v2*v2 + v3*v3;
        ps  += kv0 + kv1;
        pss += kv0*kv0 + kv1*kv1;
    }
    #pragma unroll
    for (int off = 16; off; off >>= 1) {
        s   += __shfl_xor_sync(0xFFFFFFFFu, s,   off);
        ss  += __shfl_xor_sync(0xFFFFFFFFu, ss,  off);
        ps  += __shfl_xor_sync(0xFFFFFFFFu, ps,  off);
        pss += __shfl_xor_sync(0xFFFFFFFFu, pss, off);
    }
    float varx = (ss  - s  * s  * (1.f / 1024.f)) * (1.f / 1023.f);
    float varp = (pss - ps * ps * (1.f / 1024.f)) * (1.f / 1023.f);
    varp = fmaxf(varp, 1e-9f);
    const float sc = sqrtf(varx / varp);

    uint32_t* dc = reinterpret_cast<uint32_t*>(g_actc + (size_t)row * 512);
    #pragma unroll
    for (int jj = 0; jj < 8; jj++) {
        __half2 hc = __floats2half2_rn(sc * k0v[jj], sc * k1v[jj]);
        dc[lane + 32 * jj] = *reinterpret_cast<uint32_t*>(&hc);

        uint32_t m = (uint32_t)nib[jj] << (4 * (lane & 7));
        m |= __shfl_xor_sync(0xFFFFFFFFu, m, 1);
        m |= __shfl_xor_sync(0xFFFFFFFFu, m, 2);
        m |= __shfl_xor_sync(0xFFFFFFFFu, m, 4);
        if ((lane & 7) == 0)
            canw[wid * 32 + 4 * jj + (lane >> 3)] = m;
    }
    __syncthreads();

    // canonical words to global (for verify/densify):
    g_can[(size_t)blockIdx.x * 512 + tid] = canw[tid];

    // Compose: each thread emits one final per-thread metadata word.
    // Output layout: g_meta[(mb*32 + kw)*16 + (g*2 + jpar)]
    const int fl   = g_flag;
    const int kw   = tid >> 4;
    const int idx  = tid & 15;
    const int g    = idx >> 1;
    const int jpar = idx & 1;
    uint32_t wg  = canw[g * 32 + kw];
    uint32_t wg8 = canw[(g + 8) * 32 + kw];
    g_meta[((size_t)blockIdx.x * 32 + kw) * 16 + idx] =
        compose_meta(fl, wg, wg8, jpar);
}

// =====================================================================
// Kernel 3a: SPARSE GEMM. CTA 128x128, warp 64x32, 3 stages, 2 CTAs/SM.
// B fragments double-buffered (R13/R15 exact — best measured config).
// =====================================================================
static constexpr int SA_ROWB = 80;
static constexpr int SB_ROWB = 144;
static constexpr int SA_BYTES = 128 * SA_ROWB;   // 10240
static constexpr int SB_BYTES = 128 * SB_ROWB;   // 18432
static constexpr int SOFF_B = SA_BYTES;
static constexpr int SOFF_M = SA_BYTES + SB_BYTES;
static constexpr int SSTAGE = SOFF_M + 1024;     // 29696
static constexpr unsigned SSMEM = 3 * SSTAGE;    // 89088

__global__ void __launch_bounds__(256, 2) gemm_sparse(float* __restrict__ C) {
    const int fl = g_flag;
    if (fl >= NCAND) return;

    extern __shared__ char smem[];
    const int tid  = threadIdx.x;
    const int lane = tid & 31;
    const int w    = tid >> 5;
    const int wm   = w & 1;
    const int wn   = w >> 1;
    const int g    = lane >> 2;
    const int t    = lane & 3;
    const int jpar = lane & 1;

    const int m0 = blockIdx.y * 128;
    const int n0 = blockIdx.x * 128;

    float acc[4][4][4];
    #pragma unroll
    for (int i = 0; i < 4; i++)
        #pragma unroll
        for (int jj = 0; jj < 4; jj++)
            #pragma unroll
            for (int q = 0; q < 4; q++) acc[i][jj][q] = 0.f;

    const __half*   Agb = g_actc + (size_t)m0 * 512;
    const __half*   Bgb = g_wt   + (size_t)n0 * 1024;
    const uint32_t* Mgb = g_meta + (size_t)(m0 >> 4) * 512;

    const uint32_t smem_base = (uint32_t)__cvta_generic_to_shared(smem);
    const int j8 = lane >> 3, r8 = lane & 7;
    const uint32_t a_lane_off =
        (uint32_t)((wm * 64 + (j8 & 1) * 8 + r8) * SA_ROWB + (j8 >> 1) * 16);
    const uint32_t b_lane_off = (uint32_t)(SOFF_B + r8 * SB_ROWB + j8 * 16);
    const uint32_t m_lane_off = (uint32_t)(SOFF_M + (g * 2 + jpar) * 4);

    auto load_stage = [&](int kt, int st_i) {
        char* st = smem + st_i * SSTAGE;
        const __half* Ag = Agb + kt * 32;
        const __half* Bg = Bgb + kt * 64;
        #pragma unroll
        for (int i = 0; i < 2; i++) {
            int ch = tid + i * 256;
            int r = ch >> 2, c = ch & 3;
            cp16(st + r * SA_ROWB + c * 16, Ag + (size_t)r * 512 + c * 8);
        }
        #pragma unroll
        for (int i = 0; i < 4; i++) {
            int ch = tid + i * 256;
            int r = ch >> 3, c = ch & 7;
            cp16(st + SOFF_B + r * SB_ROWB + c * 16, Bg + (size_t)r * 1024 + c * 8);
        }
        if (tid < 64) {
            int mb = tid >> 3, c = tid & 7;
            cp16(st + SOFF_M + mb * 128 + c * 16,
                 Mgb + ((size_t)mb * 32 + kt * 2) * 16 + c * 4);
        }
        cp_commit();
    };

    load_stage(0, 0);
    load_stage(1, 1);

    for (int kt = 0; kt < 16; kt++) {
        cp_wait<1>();
        __syncthreads();

        if (kt + 2 < 16) load_stage(kt + 2, (kt + 2) % 3);

        const uint32_t st = smem_base + (uint32_t)((kt % 3) * SSTAGE);
        #pragma unroll
        for (int kk = 0; kk < 2; kk++) {
            uint32_t E[4];
            #pragma unroll
            for (int mt = 0; mt < 4; mt++)
                E[mt] = lds32(st + m_lane_off
                              + (uint32_t)((wm * 4 + mt) * 128 + kk * 64));
            uint32_t a[4][4];
            #pragma unroll
            for (int mt = 0; mt < 4; mt++)
                ldsm_x4(a[mt], st + a_lane_off + mt * (16 * SA_ROWB) + kk * 32);

            // B fragment double buffer: break the ldsm->mma use chain.
            uint32_t b2[2][4];
            const uint32_t bb = st + b_lane_off + (uint32_t)(wn * 32 * SB_ROWB)
                              + (uint32_t)(kk * 64);
            ldsm_x4(b2[0], bb);
            if (fl >= 5) {
                #pragma unroll
                for (int nt = 0; nt < 4; nt++) {
                    if (nt < 3)
                        ldsm_x4(b2[(nt + 1) & 1], bb + (nt + 1) * 8 * SB_ROWB);
                    #pragma unroll
                    for (int mt = 0; mt < 4; mt++)
                        mma_spp(acc[mt][nt], a[mt], b2[nt & 1], E[mt]);
                }
            } else {
                #pragma unroll
                for (int nt = 0; nt < 4; nt++) {
                    if (nt < 3)
                        ldsm_x4(b2[(nt + 1) & 1], bb + (nt + 1) * 8 * SB_ROWB);
                    #pragma unroll
                    for (int mt = 0; mt < 4; mt++)
                        mma_spo(acc[mt][nt], a[mt], b2[nt & 1], E[mt]);
                }
            }
        }
    }

    #pragma unroll
    for (int mt = 0; mt < 4; mt++) {
        const int row = m0 + wm * 64 + mt * 16 + g;
        #pragma unroll
        for (int nt = 0; nt < 4; nt++) {
            const int col = n0 + wn * 32 + nt * 8 + 2 * t;
            float2 v0 = make_float2(acc[mt][nt][0], acc[mt][nt][1]);
            float2 v1 = make_float2(acc[mt][nt][2], acc[mt][nt][3]);
            *reinterpret_cast<float2*>(&C[(size_t)row * 1024 + col])       = v0;
            *reinterpret_cast<float2*>(&C[(size_t)(row + 8) * 1024 + col]) = v1;
        }
    }
}

// =====================================================================
// Kernel 4: verify (slim). 128 blocks = 16 rows x 8 n-chunks; 16 cols
// per block, offsets vary per row -> all positions mod 16 covered.
// =====================================================================
__global__ void __launch_bounds__(256) verify_kernel(const float* __restrict__ C) {
    if (g_flag >= NCAND) {
        if (blockIdx.x == 0 && threadIdx.x == 0) g_ok = 0;
        return;
    }
    __shared__ __half arow[1024];
    const int tid  = threadIdx.x;
    const int wid  = tid >> 5;
    const int lane = tid & 31;
    const int rsel = blockIdx.x >> 3;
    const int row  = rsel * 2048 + ((rsel * 1337) & 2047);
    const int colbase = (blockIdx.x & 7) * 128;

    {
        uint32_t pair = reinterpret_cast<const uint32_t*>(
                            g_actc + (size_t)row * 512)[tid];
        uint32_t word = g_can[(size_t)row * 32 + (tid >> 3)];
        uint32_t nb = (word >> (4 * (tid & 7))) & 0xFu;
        int e0 = nb & 3, e1 = (nb >> 2) & 3;
        __half2 hv = *reinterpret_cast<__half2*>(&pair);
        __half z = __float2half(0.f);
        __half v[4] = { z, z, z, z };
        v[e0] = __low2half(hv);
        v[e1] = __high2half(hv);
        arow[4 * tid + 0] = v[0];
        arow[4 * tid + 1] = v[1];
        arow[4 * tid + 2] = v[2];
        arow[4 * tid + 3] = v[3];
    }
    __syncthreads();

    const __half2* a2 = reinterpret_cast<const __half2*>(arow);
    #pragma unroll
    for (int c0 = 0; c0 < 2; c0++) {
        const int col = colbase + wid * 16 + c0 * 8 + (rsel & 7);
        const __half2* w2 =
            reinterpret_cast<const __half2*>(g_wt + (size_t)col * 1024);
        float sum = 0.f;
        for (int k = lane; k < 512; k += 32) {
            float2 af = __half22float2(a2[k]);
            float2 wf = __half22float2(w2[k]);
            sum = fmaf(af.x, wf.x, fmaf(af.y, wf.y, sum));
        }
        #pragma unroll
        for (int off = 16; off; off >>= 1)
            sum += __shfl_xor_sync(0xFFFFFFFFu, sum, off);
        if (lane == 0) {
            float got = C[(size_t)row * 1024 + col];
            if (fabsf(got - sum) > 0.02f * (fabsf(sum) + 0.25f)) g_ok = 0;
        }
    }
}

// =====================================================================
// Kernel 5: densify (iff !g_ok). PERSISTENT: 148 blocks, strided loop.
// =====================================================================
__global__ void __launch_bounds__(256) densify_kernel() {
    if (g_ok) return;
    for (int base = blockIdx.x; base < 32768; base += 148) {
        int gi = base * 256 + threadIdx.x;
        int row = gi >> 8, gg = gi & 255;
        uint32_t pair = reinterpret_cast<const uint32_t*>(
                            g_actc + (size_t)row * 512)[gg];
        uint32_t word = g_can[(size_t)row * 32 + (gg >> 3)];
        uint32_t nb = (word >> (4 * (gg & 7))) & 0xFu;
        int e0 = nb & 3, e1 = (nb >> 2) & 3;
        __half2 hv = *reinterpret_cast<__half2*>(&pair);
        __half z = __float2half(0.f);
        __half v[4] = { z, z, z, z };
        v[e0] = __low2half(hv);
        v[e1] = __high2half(hv);
        __half2 lo = __halves2half2(v[0], v[1]);
        __half2 hi = __halves2half2(v[2], v[3]);
        uint2 o;
        o.x = *reinterpret_cast<uint32_t*>(&lo);
        o.y = *reinterpret_cast<uint32_t*>(&hi);
        reinterpret_cast<uint2*>(g_actd)[gi] = o;
    }
}

// =====================================================================
// Kernel 3b: DENSE GEMM fallback (iff !g_ok). PERSISTENT: 296 blocks.
// =====================================================================
static constexpr int DLDH = 40;
static constexpr int DA_ELTS = 128 * DLDH;
static constexpr int DSTAGE_ELTS = 2 * DA_ELTS;
static constexpr unsigned DSMEM = 4 * DSTAGE_ELTS * 2;           // 81920

__global__ void __launch_bounds__(256, 2) gemm_dense(float* __restrict__ C) {
    if (g_ok) return;

    extern __shared__ __half dsm[];
    const int tid  = threadIdx.x;
    const int lane = tid & 31;
    const int w    = tid >> 5;
    const int wm   = w & 1;
    const int wn   = w >> 1;
    const int g    = lane >> 2;
    const int t    = lane & 3;

    const uint32_t smem_base = (uint32_t)__cvta_generic_to_shared(dsm);
    const int j8 = lane >> 3, r8 = lane & 7;
    const uint32_t a_lane_off =
        (uint32_t)((wm * 64 + (j8 & 1) * 8 + r8) * 80 + (j8 >> 1) * 16);
    const uint32_t b_lane_off =
        (uint32_t)(DA_ELTS * 2 + (wn * 32 + (j8 >> 1) * 8 + r8) * 80 + (j8 & 1) * 16);

    for (int tile = blockIdx.x; tile < 2048; tile += 296) {
        const int m0 = (tile >> 3) * 128;
        const int n0 = (tile & 7) * 128;

        float acc[4][4][4];
        #pragma unroll
        for (int i = 0; i < 4; i++)
            #pragma unroll
            for (int jj = 0; jj < 4; jj++)
                #pragma unroll
                for (int q = 0; q < 4; q++) acc[i][jj][q] = 0.f;

        const __half* Agb = g_actd + (size_t)m0 * 1024;
        const __half* Bgb = g_wt   + (size_t)n0 * 1024;

        auto load_stage = [&](int kt, int st_i) {
            __half* As = dsm + st_i * DSTAGE_ELTS;
            __half* Bs = As + DA_ELTS;
            const __half* Ag = Agb + kt * 32;
            const __half* Bg = Bgb + kt * 32;
            #pragma unroll
            for (int i = 0; i < 2; i++) {
                int ch = tid + i * 256;
                int r = ch >> 2, c = ch & 3;
                cp16(As + r * DLDH + c * 8, Ag + (size_t)r * 1024 + c * 8);
            }
            #pragma unroll
            for (int i = 0; i < 2; i++) {
                int ch = tid + i * 256;
                int r = ch >> 2, c = ch & 3;
                cp16(Bs + r * DLDH + c * 8, Bg + (size_t)r * 1024 + c * 8);
            }
            cp_commit();
        };

        load_stage(0, 0);
        load_stage(1, 1);
        load_stage(2, 2);

        for (int kt = 0; kt < 32; kt++) {
            cp_wait<2>();
            __syncthreads();

            if (kt + 3 < 32) load_stage(kt + 3, (kt + 3) & 3);

            const uint32_t st = smem_base + (uint32_t)((kt & 3) * DSTAGE_ELTS * 2);
            const uint32_t abase = st + a_lane_off;
            const uint32_t bbase = st + b_lane_off;

            #pragma unroll
            for (int kk = 0; kk < 2; kk++) {
                uint32_t a[4][4];
                #pragma unroll
                for (int mt = 0; mt < 4; mt++)
                    ldsm_x4(a[mt], abase + mt * (16 * 80) + kk * 32);
                uint32_t b[2][4];
                #pragma unroll
                for (int np = 0; np < 2; np++)
                    ldsm_x4(b[np], bbase + np * (16 * 80) + kk * 32);
                #pragma unroll
                for (int mt = 0; mt < 4; mt++)
                    #pragma unroll
                    for (int nt = 0; nt < 4; nt++)
                        mma_f16(acc[mt][nt], a[mt], &b[nt >> 1][(nt & 1) * 2]);
            }
        }

        #pragma unroll
        for (int mt = 0; mt < 4; mt++) {
            const int row = m0 + wm * 64 + mt * 16 + g;
            #pragma unroll
            for (int nt = 0; nt < 4; nt++) {
                const int col = n0 + wn * 32 + nt * 8 + 2 * t;
                float2 v0 = make_float2(acc[mt][nt][0], acc[mt][nt][1]);
                float2 v1 = make_float2(acc[mt][nt][2], acc[mt][nt][3]);
                *reinterpret_cast<float2*>(&C[(size_t)row * 1024 + col])       = v0;
                *reinterpret_cast<float2*>(&C[(size_t)(row + 8) * 1024 + col]) = v1;
            }
        }

        cp_wait<0>();
        __syncthreads();
    }
}

// =====================================================================
// Host launcher
// =====================================================================
extern "C" void kernel_launch(void* const* d_in, const int* in_sizes, int n_in,
                              void* d_out, int out_size) {
    const float* x = (const float*)d_in[0];
    const float* w = (const float*)d_in[1];
    if (n_in >= 2 && in_sizes[0] == 1048576 && in_sizes[1] != 1048576) {
        const float* tswap = x; x = w; w = tswap;
    }
    float* out = (float*)d_out;

    probe_kernel<<<1, 32>>>();
    prep_kernel<<<2176, 512>>>(x, w);     // 2048 act blocks + 128 weight blocks

    cudaFuncSetAttribute(gemm_sparse,
                         cudaFuncAttributeMaxDynamicSharedMemorySize, SSMEM);
    cudaFuncSetAttribute(gemm_dense,
                         cudaFuncAttributeMaxDynamicSharedMemorySize, DSMEM);

    gemm_sparse<<<dim3(8, 256), 256, SSMEM>>>(out);
    verify_kernel<<<128, 256>>>(out);
    densify_kernel<<<148, 256>>>();
    gemm_dense<<<296, 256, DSMEM>>>(out);
}